// round 1
// baseline (speedup 1.0000x reference)
#include <cuda_runtime.h>
#include <math.h>

#define S_LEN 2048
#define HID   2048
#define NH    32
#define NKV   4
#define HD    128
#define NQ    (NH * HD)    // 4096
#define NKVD  (NKV * HD)   // 512

// Scratch (device globals — no allocation allowed in kernel_launch)
__device__ float g_q[S_LEN * NQ];      // 32 MB
__device__ float g_k[S_LEN * NKVD];    //  4 MB
__device__ float g_v[S_LEN * NKVD];    //  4 MB
__device__ float g_attn[S_LEN * NQ];   // 32 MB

// ---------------------------------------------------------------------------
// Classic 128x128x8 SGEMM, 256 threads, 8x8 micro-tile. A: MxK row-major,
// B: KxN row-major, C: MxN row-major. Requires M%128==0, N%128==0, K%8==0.
// ---------------------------------------------------------------------------
__global__ __launch_bounds__(256) void sgemm128(
    const float* __restrict__ A, const float* __restrict__ B,
    float* __restrict__ C, int M, int N, int K)
{
    __shared__ float As[8][128];   // stored transposed: As[k][m]
    __shared__ float Bs[8][128];

    const int tid = threadIdx.x;
    const int tx = tid & 15;       // 16 threads across N
    const int ty = tid >> 4;       // 16 threads across M
    const int m0 = blockIdx.y << 7;
    const int n0 = blockIdx.x << 7;

    float acc[8][8];
#pragma unroll
    for (int i = 0; i < 8; i++)
#pragma unroll
        for (int j = 0; j < 8; j++) acc[i][j] = 0.0f;

    const int arow = tid >> 1;            // 128 rows, 2 float4/row
    const int acol = (tid & 1) << 2;
    const int brow = tid >> 5;            // 8 rows, 32 float4/row
    const int bcol = (tid & 31) << 2;

    const float* Ap = A + (size_t)(m0 + arow) * K + acol;
    const float* Bp = B + (size_t)brow * N + n0 + bcol;

    for (int k0 = 0; k0 < K; k0 += 8) {
        float4 a4 = *(const float4*)Ap;
        float4 b4 = *(const float4*)Bp;
        As[acol + 0][arow] = a4.x;
        As[acol + 1][arow] = a4.y;
        As[acol + 2][arow] = a4.z;
        As[acol + 3][arow] = a4.w;
        *(float4*)(&Bs[brow][bcol]) = b4;
        __syncthreads();

#pragma unroll
        for (int kk = 0; kk < 8; kk++) {
            float ra[8], rb[8];
            *(float4*)(ra)     = *(const float4*)&As[kk][(ty << 3)];
            *(float4*)(ra + 4) = *(const float4*)&As[kk][(ty << 3) + 4];
            *(float4*)(rb)     = *(const float4*)&Bs[kk][(tx << 3)];
            *(float4*)(rb + 4) = *(const float4*)&Bs[kk][(tx << 3) + 4];
#pragma unroll
            for (int i = 0; i < 8; i++)
#pragma unroll
                for (int j = 0; j < 8; j++)
                    acc[i][j] = fmaf(ra[i], rb[j], acc[i][j]);
        }
        __syncthreads();

        Ap += 8;
        Bp += (size_t)8 * N;
    }

#pragma unroll
    for (int i = 0; i < 8; i++) {
        float* Cp = C + (size_t)(m0 + (ty << 3) + i) * N + n0 + (tx << 3);
        *(float4*)(Cp)     = make_float4(acc[i][0], acc[i][1], acc[i][2], acc[i][3]);
        *(float4*)(Cp + 4) = make_float4(acc[i][4], acc[i][5], acc[i][6], acc[i][7]);
    }
}

// ---------------------------------------------------------------------------
// Fused RMSNorm + RoPE, in-place on x[S][heads*HD]. One block = one (s, head)
// row of HD=128 elements, 128 threads.
// ---------------------------------------------------------------------------
__global__ __launch_bounds__(128) void rmsnorm_rope(
    float* __restrict__ x, const float* __restrict__ w,
    const float* __restrict__ cs, const float* __restrict__ sn, int heads)
{
    const int b = blockIdx.x;
    const int s = b / heads;
    const int h = b - s * heads;
    const int d = threadIdx.x;

    float* row = x + ((size_t)s * heads + h) * HD;
    float v = row[d];

    float ssq = v * v;
#pragma unroll
    for (int off = 16; off > 0; off >>= 1)
        ssq += __shfl_xor_sync(0xffffffffu, ssq, off);

    __shared__ float red[4];
    __shared__ float sh[HD];
    if ((d & 31) == 0) red[d >> 5] = ssq;
    __syncthreads();
    float tot = red[0] + red[1] + red[2] + red[3];

    float xn = v * rsqrtf(tot * (1.0f / HD) + 1e-6f) * w[d];
    sh[d] = xn;
    __syncthreads();

    float partner = (d < 64) ? -sh[d + 64] : sh[d - 64];
    row[d] = xn * cs[s * HD + d] + partner * sn[s * HD + d];
}

// ---------------------------------------------------------------------------
// Flash attention (fp32, causal, GQA with G=8).
// Block = (head, 32-query tile), 128 threads (4 warps).
// Each thread: 8 query rows (ty + 4i) x 4 head-dim cols (tx + 32j).
// K and V share one smem buffer (load K -> scores -> load V -> PV).
// ---------------------------------------------------------------------------
__global__ __launch_bounds__(128) void flash_attn(
    const float* __restrict__ q, const float* __restrict__ k,
    const float* __restrict__ v, float* __restrict__ o)
{
    const int h   = blockIdx.x;        // 0..31
    const int mb  = blockIdx.y;        // 0..63
    const int kvh = h >> 3;            // G = 8
    const int m0  = mb << 5;

    __shared__ float Qs[32][128];
    __shared__ float KV[32][132];      // pad 132: conflict-free float4 K reads
    __shared__ float Ps[32][32];

    const int tid = threadIdx.x;
    const int tx = tid & 31;
    const int ty = tid >> 5;

    for (int idx = tid; idx < 32 * 128; idx += 128) {
        int r = idx >> 7, d = idx & 127;
        Qs[r][d] = q[(size_t)(m0 + r) * NQ + h * HD + d];
    }

    float m_i[8], l_i[8], O[8][4];
#pragma unroll
    for (int i = 0; i < 8; i++) {
        m_i[i] = -1e30f; l_i[i] = 0.0f;
        O[i][0] = O[i][1] = O[i][2] = O[i][3] = 0.0f;
    }
    const float scale = 0.08838834764831845f;   // 1/sqrt(128)
    __syncthreads();

    for (int kb = 0; kb <= mb; kb++) {
        const int kbase = kb << 5;

        // Load K tile
        for (int idx = tid; idx < 32 * 128; idx += 128) {
            int c = idx >> 7, d = idx & 127;
            KV[c][d] = k[(size_t)(kbase + c) * NKVD + kvh * HD + d];
        }
        __syncthreads();

        // Scores: s[i] = Q[ty+4i] . K[tx]
        float s[8];
#pragma unroll
        for (int i = 0; i < 8; i++) s[i] = 0.0f;
#pragma unroll 4
        for (int d4 = 0; d4 < 32; d4++) {
            float4 k4 = *(const float4*)&KV[tx][d4 << 2];
#pragma unroll
            for (int i = 0; i < 8; i++) {
                float4 q4 = *(const float4*)&Qs[ty + (i << 2)][d4 << 2];
                s[i] = fmaf(q4.x, k4.x, s[i]);
                s[i] = fmaf(q4.y, k4.y, s[i]);
                s[i] = fmaf(q4.z, k4.z, s[i]);
                s[i] = fmaf(q4.w, k4.w, s[i]);
            }
        }
        __syncthreads();   // done reading K

        // Load V tile into same buffer
        for (int idx = tid; idx < 32 * 128; idx += 128) {
            int c = idx >> 7, d = idx & 127;
            KV[c][d] = v[(size_t)(kbase + c) * NKVD + kvh * HD + d];
        }

        // Online softmax (register/shuffle only)
#pragma unroll
        for (int i = 0; i < 8; i++) {
            int qrow = m0 + ty + (i << 2);
            float sv = (kbase + tx > qrow) ? -1e30f : s[i] * scale;
            float mx = sv;
#pragma unroll
            for (int off = 16; off > 0; off >>= 1)
                mx = fmaxf(mx, __shfl_xor_sync(0xffffffffu, mx, off));
            float mnew  = fmaxf(m_i[i], mx);
            float alpha = __expf(m_i[i] - mnew);
            float p     = __expf(sv - mnew);
            float psum  = p;
#pragma unroll
            for (int off = 16; off > 0; off >>= 1)
                psum += __shfl_xor_sync(0xffffffffu, psum, off);
            l_i[i] = l_i[i] * alpha + psum;
            m_i[i] = mnew;
            O[i][0] *= alpha; O[i][1] *= alpha; O[i][2] *= alpha; O[i][3] *= alpha;
            Ps[ty + (i << 2)][tx] = p;
        }
        __syncthreads();   // Ps + V visible

        // O += P @ V
#pragma unroll 4
        for (int c = 0; c < 32; c++) {
            float v0 = KV[c][tx];
            float v1 = KV[c][tx + 32];
            float v2 = KV[c][tx + 64];
            float v3 = KV[c][tx + 96];
#pragma unroll
            for (int i = 0; i < 8; i++) {
                float p = Ps[ty + (i << 2)][c];
                O[i][0] = fmaf(p, v0, O[i][0]);
                O[i][1] = fmaf(p, v1, O[i][1]);
                O[i][2] = fmaf(p, v2, O[i][2]);
                O[i][3] = fmaf(p, v3, O[i][3]);
            }
        }
        __syncthreads();   // done reading V/Ps before next tile
    }

#pragma unroll
    for (int i = 0; i < 8; i++) {
        float inv = 1.0f / l_i[i];
        size_t base = (size_t)(m0 + ty + (i << 2)) * NQ + h * HD;
        o[base + tx]      = O[i][0] * inv;
        o[base + tx + 32] = O[i][1] * inv;
        o[base + tx + 64] = O[i][2] * inv;
        o[base + tx + 96] = O[i][3] * inv;
    }
}

// ---------------------------------------------------------------------------
extern "C" void kernel_launch(void* const* d_in, const int* in_sizes, int n_in,
                              void* d_out, int out_size)
{
    (void)in_sizes; (void)n_in; (void)out_size;
    const float* x  = (const float*)d_in[0];
    const float* wq = (const float*)d_in[1];
    const float* wk = (const float*)d_in[2];
    const float* wv = (const float*)d_in[3];
    const float* wo = (const float*)d_in[4];
    const float* qn = (const float*)d_in[5];
    const float* kn = (const float*)d_in[6];
    const float* cs = (const float*)d_in[7];
    const float* sn = (const float*)d_in[8];
    float* out = (float*)d_out;

    float *q, *k, *v, *attn;
    cudaGetSymbolAddress((void**)&q,    g_q);
    cudaGetSymbolAddress((void**)&k,    g_k);
    cudaGetSymbolAddress((void**)&v,    g_v);
    cudaGetSymbolAddress((void**)&attn, g_attn);

    // Projections
    sgemm128<<<dim3(NQ / 128,   S_LEN / 128), 256>>>(x, wq, q, S_LEN, NQ,   HID);
    sgemm128<<<dim3(NKVD / 128, S_LEN / 128), 256>>>(x, wk, k, S_LEN, NKVD, HID);
    sgemm128<<<dim3(NKVD / 128, S_LEN / 128), 256>>>(x, wv, v, S_LEN, NKVD, HID);

    // RMSNorm + RoPE (in place)
    rmsnorm_rope<<<S_LEN * NH,  128>>>(q, qn, cs, sn, NH);
    rmsnorm_rope<<<S_LEN * NKV, 128>>>(k, kn, cs, sn, NKV);

    // Causal GQA flash attention
    flash_attn<<<dim3(NH, S_LEN / 32), 128>>>(q, k, v, attn);

    // Output projection
    sgemm128<<<dim3(HID / 128, S_LEN / 128), 256>>>(attn, wo, out, S_LEN, HID, NQ);
}

// round 3
// speedup vs baseline: 2.3883x; 2.3883x over previous
#include <cuda_runtime.h>
#include <cuda_bf16.h>
#include <mma.h>
#include <cstdint>
#include <math.h>

using namespace nvcuda;

#define S_LEN 2048
#define HID   2048
#define NH    32
#define NKV   4
#define HD    128
#define NQ    (NH * HD)    // 4096
#define NKVD  (NKV * HD)   // 512

// ---------------------------------------------------------------------------
// Scratch (device globals — no allocation allowed)
// ---------------------------------------------------------------------------
__device__ float g_q[S_LEN * NQ];
__device__ float g_k[S_LEN * NKVD];
__device__ float g_v[S_LEN * NKVD];
__device__ float g_attn[S_LEN * NQ];

__device__ __nv_bfloat16 g_xh[S_LEN * HID];
__device__ __nv_bfloat16 g_xl[S_LEN * HID];
__device__ __nv_bfloat16 g_wqTh[NQ * HID];
__device__ __nv_bfloat16 g_wqTl[NQ * HID];
__device__ __nv_bfloat16 g_wkTh[NKVD * HID];
__device__ __nv_bfloat16 g_wkTl[NKVD * HID];
__device__ __nv_bfloat16 g_wvTh[NKVD * HID];
__device__ __nv_bfloat16 g_wvTl[NKVD * HID];
__device__ __nv_bfloat16 g_woTh[HID * NQ];
__device__ __nv_bfloat16 g_woTl[HID * NQ];
__device__ __nv_bfloat16 g_ath[S_LEN * NQ];
__device__ __nv_bfloat16 g_atl[S_LEN * NQ];

// ---------------------------------------------------------------------------
// helpers
// ---------------------------------------------------------------------------
__device__ __forceinline__ uint32_t smem_u32(const void* p) {
    uint32_t a;
    asm("{ .reg .u64 t; cvta.to.shared.u64 t, %1; cvt.u32.u64 %0, t; }"
        : "=r"(a) : "l"(p));
    return a;
}

__device__ __forceinline__ void cpa16(uint32_t dst, const void* src) {
    asm volatile(
        "{\n\t.reg .u64 g;\n\tcvta.to.global.u64 g, %1;\n\t"
        "cp.async.cg.shared.global [%0], [g], 16;\n\t}"
        :: "r"(dst), "l"(src) : "memory");
}
#define CPA_COMMIT() asm volatile("cp.async.commit_group;" ::: "memory")
#define CPA_WAIT1()  asm volatile("cp.async.wait_group 1;" ::: "memory")
#define CPA_WAIT0()  asm volatile("cp.async.wait_group 0;" ::: "memory")

// ---------------------------------------------------------------------------
// fp32 -> bf16 hi/lo split (elementwise)
// ---------------------------------------------------------------------------
__global__ void split_bf16(const float* __restrict__ in,
                           __nv_bfloat16* __restrict__ oh,
                           __nv_bfloat16* __restrict__ ol, int n)
{
    int i = blockIdx.x * blockDim.x + threadIdx.x;
    if (i < n) {
        float x = in[i];
        __nv_bfloat16 h = __float2bfloat16(x);
        oh[i] = h;
        ol[i] = __float2bfloat16(x - __bfloat162float(h));
    }
}

// ---------------------------------------------------------------------------
// Transpose [R][C] fp32 -> [C][R] bf16 hi/lo
// ---------------------------------------------------------------------------
__global__ void transpose_split(const float* __restrict__ in,
                                __nv_bfloat16* __restrict__ oh,
                                __nv_bfloat16* __restrict__ ol, int R, int C)
{
    __shared__ float t[32][33];
    int c0 = blockIdx.x << 5, r0 = blockIdx.y << 5;
    int x = threadIdx.x, y = threadIdx.y;
#pragma unroll
    for (int j = y; j < 32; j += 8)
        t[j][x] = in[(size_t)(r0 + j) * C + c0 + x];
    __syncthreads();
#pragma unroll
    for (int j = y; j < 32; j += 8) {
        float v = t[x][j];
        __nv_bfloat16 h = __float2bfloat16(v);
        size_t o = (size_t)(c0 + j) * R + r0 + x;
        oh[o] = h;
        ol[o] = __float2bfloat16(v - __bfloat162float(h));
    }
}

// ---------------------------------------------------------------------------
// bf16x3 wmma GEMM: C[m][n] = sum_k A[m][k] * BT[n][k]
// A (hi/lo): [M][K] bf16 row-major; BT (hi/lo): [N][K] bf16 row-major.
// CTA tile 128x128, 256 threads (8 warps, 4x2), warp tile 32x64.
// K chunks of 32, 2-stage cp.async double buffer.
// ---------------------------------------------------------------------------
#define GBK    32
#define GPAD   40                       // row stride, elements (80 B, %16B==0)
#define GTILE  (128 * GPAD)             // one tile (elements)
#define GSTAGE (4 * GTILE)              // Ah, Al, Bh, Bl
#define GEMM_SMEM_BYTES (2 * GSTAGE * 2)

__global__ void __launch_bounds__(256) gemm_wmma_bf16x3(
    const __nv_bfloat16* __restrict__ Ah, const __nv_bfloat16* __restrict__ Al,
    const __nv_bfloat16* __restrict__ Bh, const __nv_bfloat16* __restrict__ Bl,
    float* __restrict__ C, int N, int K)
{
    extern __shared__ __nv_bfloat16 sm[];
    const int tid = threadIdx.x;
    const int wid = tid >> 5;
    const int m0 = blockIdx.y << 7, n0 = blockIdx.x << 7;
    const int wm = wid >> 1;            // 0..3 -> 32-row slab
    const int wn = wid & 1;             // 0..1 -> 64-col slab

    wmma::fragment<wmma::accumulator, 16, 16, 16, float> acc[2][4];
#pragma unroll
    for (int i = 0; i < 2; i++)
#pragma unroll
        for (int j = 0; j < 4; j++)
            wmma::fill_fragment(acc[i][j], 0.0f);

    const int lrow = tid >> 1;          // 0..127
    const int cb   = (tid & 1) * 2;     // 16B chunk base (0 or 2)

    const __nv_bfloat16* gbase[4] = {Ah, Al, Bh, Bl};
    const int grow0[4] = {m0, m0, n0, n0};

    const int nck = K / GBK;

    auto load_stage = [&](int ck, int s) {
        const int k0 = ck * GBK;
#pragma unroll
        for (int t = 0; t < 4; t++) {
            uint32_t dst = smem_u32(sm + s * GSTAGE + t * GTILE) + lrow * (GPAD * 2);
            const __nv_bfloat16* src = gbase[t] + (size_t)(grow0[t] + lrow) * K + k0;
            cpa16(dst + (cb + 0) * 16, src + (cb + 0) * 8);
            cpa16(dst + (cb + 1) * 16, src + (cb + 1) * 8);
        }
        CPA_COMMIT();
    };

    load_stage(0, 0);

    for (int ck = 0; ck < nck; ck++) {
        if (ck + 1 < nck) {
            load_stage(ck + 1, (ck + 1) & 1);
            CPA_WAIT1();
        } else {
            CPA_WAIT0();
        }
        __syncthreads();

        const int s = ck & 1;
        const __nv_bfloat16* pAh = sm + s * GSTAGE + 0 * GTILE + wm * 32 * GPAD;
        const __nv_bfloat16* pAl = sm + s * GSTAGE + 1 * GTILE + wm * 32 * GPAD;
        const __nv_bfloat16* pBh = sm + s * GSTAGE + 2 * GTILE + wn * 64 * GPAD;
        const __nv_bfloat16* pBl = sm + s * GSTAGE + 3 * GTILE + wn * 64 * GPAD;

#pragma unroll
        for (int kk = 0; kk < GBK; kk += 16) {
            wmma::fragment<wmma::matrix_a, 16, 16, 16, __nv_bfloat16, wmma::row_major> ah[2], al[2];
            wmma::fragment<wmma::matrix_b, 16, 16, 16, __nv_bfloat16, wmma::col_major> bh[4], bl[4];
#pragma unroll
            for (int i = 0; i < 2; i++) {
                wmma::load_matrix_sync(ah[i], pAh + i * 16 * GPAD + kk, GPAD);
                wmma::load_matrix_sync(al[i], pAl + i * 16 * GPAD + kk, GPAD);
            }
#pragma unroll
            for (int j = 0; j < 4; j++) {
                wmma::load_matrix_sync(bh[j], pBh + j * 16 * GPAD + kk, GPAD);
                wmma::load_matrix_sync(bl[j], pBl + j * 16 * GPAD + kk, GPAD);
            }
#pragma unroll
            for (int i = 0; i < 2; i++)
#pragma unroll
                for (int j = 0; j < 4; j++) {
                    wmma::mma_sync(acc[i][j], ah[i], bh[j], acc[i][j]);
                    wmma::mma_sync(acc[i][j], ah[i], bl[j], acc[i][j]);
                    wmma::mma_sync(acc[i][j], al[i], bh[j], acc[i][j]);
                }
        }
        __syncthreads();
    }

    // Epilogue: store fp32 accumulators
#pragma unroll
    for (int i = 0; i < 2; i++)
#pragma unroll
        for (int j = 0; j < 4; j++) {
            float* cp = C + (size_t)(m0 + wm * 32 + i * 16) * N + n0 + wn * 64 + j * 16;
            wmma::store_matrix_sync(cp, acc[i][j], N, wmma::mem_row_major);
        }
}

// ---------------------------------------------------------------------------
// Fused RMSNorm + RoPE
// ---------------------------------------------------------------------------
__global__ __launch_bounds__(128) void rmsnorm_rope(
    float* __restrict__ x, const float* __restrict__ w,
    const float* __restrict__ cs, const float* __restrict__ sn, int heads)
{
    const int b = blockIdx.x;
    const int s = b / heads;
    const int h = b - s * heads;
    const int d = threadIdx.x;

    float* row = x + ((size_t)s * heads + h) * HD;
    float v = row[d];

    float ssq = v * v;
#pragma unroll
    for (int off = 16; off > 0; off >>= 1)
        ssq += __shfl_xor_sync(0xffffffffu, ssq, off);

    __shared__ float red[4];
    __shared__ float sh[HD];
    if ((d & 31) == 0) red[d >> 5] = ssq;
    __syncthreads();
    float tot = red[0] + red[1] + red[2] + red[3];

    float xn = v * rsqrtf(tot * (1.0f / HD) + 1e-6f) * w[d];
    sh[d] = xn;
    __syncthreads();

    float partner = (d < 64) ? -sh[d + 64] : sh[d - 64];
    row[d] = xn * cs[s * HD + d] + partner * sn[s * HD + d];
}

// ---------------------------------------------------------------------------
// Flash attention (fp32, causal, GQA) — unchanged from R1 passing version
// ---------------------------------------------------------------------------
__global__ __launch_bounds__(128) void flash_attn(
    const float* __restrict__ q, const float* __restrict__ k,
    const float* __restrict__ v, float* __restrict__ o)
{
    const int h   = blockIdx.x;
    const int mb  = blockIdx.y;
    const int kvh = h >> 3;
    const int m0  = mb << 5;

    __shared__ float Qs[32][128];
    __shared__ float KV[32][132];
    __shared__ float Ps[32][32];

    const int tid = threadIdx.x;
    const int tx = tid & 31;
    const int ty = tid >> 5;

    for (int idx = tid; idx < 32 * 128; idx += 128) {
        int r = idx >> 7, d = idx & 127;
        Qs[r][d] = q[(size_t)(m0 + r) * NQ + h * HD + d];
    }

    float m_i[8], l_i[8], O[8][4];
#pragma unroll
    for (int i = 0; i < 8; i++) {
        m_i[i] = -1e30f; l_i[i] = 0.0f;
        O[i][0] = O[i][1] = O[i][2] = O[i][3] = 0.0f;
    }
    const float scale = 0.08838834764831845f;
    __syncthreads();

    for (int kb = 0; kb <= mb; kb++) {
        const int kbase = kb << 5;

        for (int idx = tid; idx < 32 * 128; idx += 128) {
            int c = idx >> 7, d = idx & 127;
            KV[c][d] = k[(size_t)(kbase + c) * NKVD + kvh * HD + d];
        }
        __syncthreads();

        float s[8];
#pragma unroll
        for (int i = 0; i < 8; i++) s[i] = 0.0f;
#pragma unroll 4
        for (int d4 = 0; d4 < 32; d4++) {
            float4 k4 = *(const float4*)&KV[tx][d4 << 2];
#pragma unroll
            for (int i = 0; i < 8; i++) {
                float4 q4 = *(const float4*)&Qs[ty + (i << 2)][d4 << 2];
                s[i] = fmaf(q4.x, k4.x, s[i]);
                s[i] = fmaf(q4.y, k4.y, s[i]);
                s[i] = fmaf(q4.z, k4.z, s[i]);
                s[i] = fmaf(q4.w, k4.w, s[i]);
            }
        }
        __syncthreads();

        for (int idx = tid; idx < 32 * 128; idx += 128) {
            int c = idx >> 7, d = idx & 127;
            KV[c][d] = v[(size_t)(kbase + c) * NKVD + kvh * HD + d];
        }

#pragma unroll
        for (int i = 0; i < 8; i++) {
            int qrow = m0 + ty + (i << 2);
            float sv = (kbase + tx > qrow) ? -1e30f : s[i] * scale;
            float mx = sv;
#pragma unroll
            for (int off = 16; off > 0; off >>= 1)
                mx = fmaxf(mx, __shfl_xor_sync(0xffffffffu, mx, off));
            float mnew  = fmaxf(m_i[i], mx);
            float alpha = __expf(m_i[i] - mnew);
            float p     = __expf(sv - mnew);
            float psum  = p;
#pragma unroll
            for (int off = 16; off > 0; off >>= 1)
                psum += __shfl_xor_sync(0xffffffffu, psum, off);
            l_i[i] = l_i[i] * alpha + psum;
            m_i[i] = mnew;
            O[i][0] *= alpha; O[i][1] *= alpha; O[i][2] *= alpha; O[i][3] *= alpha;
            Ps[ty + (i << 2)][tx] = p;
        }
        __syncthreads();

#pragma unroll 4
        for (int c = 0; c < 32; c++) {
            float v0 = KV[c][tx];
            float v1 = KV[c][tx + 32];
            float v2 = KV[c][tx + 64];
            float v3 = KV[c][tx + 96];
#pragma unroll
            for (int i = 0; i < 8; i++) {
                float p = Ps[ty + (i << 2)][c];
                O[i][0] = fmaf(p, v0, O[i][0]);
                O[i][1] = fmaf(p, v1, O[i][1]);
                O[i][2] = fmaf(p, v2, O[i][2]);
                O[i][3] = fmaf(p, v3, O[i][3]);
            }
        }
        __syncthreads();
    }

#pragma unroll
    for (int i = 0; i < 8; i++) {
        float inv = 1.0f / l_i[i];
        size_t base = (size_t)(m0 + ty + (i << 2)) * NQ + h * HD;
        o[base + tx]      = O[i][0] * inv;
        o[base + tx + 32] = O[i][1] * inv;
        o[base + tx + 64] = O[i][2] * inv;
        o[base + tx + 96] = O[i][3] * inv;
    }
}

// ---------------------------------------------------------------------------
extern "C" void kernel_launch(void* const* d_in, const int* in_sizes, int n_in,
                              void* d_out, int out_size)
{
    (void)in_sizes; (void)n_in; (void)out_size;
    const float* x  = (const float*)d_in[0];
    const float* wq = (const float*)d_in[1];
    const float* wk = (const float*)d_in[2];
    const float* wv = (const float*)d_in[3];
    const float* wo = (const float*)d_in[4];
    const float* qn = (const float*)d_in[5];
    const float* kn = (const float*)d_in[6];
    const float* cs = (const float*)d_in[7];
    const float* sn = (const float*)d_in[8];
    float* out = (float*)d_out;

    float *q, *k, *v, *attn;
    cudaGetSymbolAddress((void**)&q,    g_q);
    cudaGetSymbolAddress((void**)&k,    g_k);
    cudaGetSymbolAddress((void**)&v,    g_v);
    cudaGetSymbolAddress((void**)&attn, g_attn);

    __nv_bfloat16 *xh, *xl, *wqTh, *wqTl, *wkTh, *wkTl, *wvTh, *wvTl, *woTh, *woTl, *ath, *atl;
    cudaGetSymbolAddress((void**)&xh,   g_xh);
    cudaGetSymbolAddress((void**)&xl,   g_xl);
    cudaGetSymbolAddress((void**)&wqTh, g_wqTh);
    cudaGetSymbolAddress((void**)&wqTl, g_wqTl);
    cudaGetSymbolAddress((void**)&wkTh, g_wkTh);
    cudaGetSymbolAddress((void**)&wkTl, g_wkTl);
    cudaGetSymbolAddress((void**)&wvTh, g_wvTh);
    cudaGetSymbolAddress((void**)&wvTl, g_wvTl);
    cudaGetSymbolAddress((void**)&woTh, g_woTh);
    cudaGetSymbolAddress((void**)&woTl, g_woTl);
    cudaGetSymbolAddress((void**)&ath,  g_ath);
    cudaGetSymbolAddress((void**)&atl,  g_atl);

    cudaFuncSetAttribute(gemm_wmma_bf16x3,
                         cudaFuncAttributeMaxDynamicSharedMemorySize, GEMM_SMEM_BYTES);

    // Split activations; transpose+split weights to [N][K] bf16
    split_bf16<<<(S_LEN * HID + 255) / 256, 256>>>(x, xh, xl, S_LEN * HID);
    transpose_split<<<dim3(NQ / 32,   HID / 32), dim3(32, 8)>>>(wq, wqTh, wqTl, HID, NQ);
    transpose_split<<<dim3(NKVD / 32, HID / 32), dim3(32, 8)>>>(wk, wkTh, wkTl, HID, NKVD);
    transpose_split<<<dim3(NKVD / 32, HID / 32), dim3(32, 8)>>>(wv, wvTh, wvTl, HID, NKVD);
    transpose_split<<<dim3(HID / 32,  NQ / 32),  dim3(32, 8)>>>(wo, woTh, woTl, NQ, HID);

    // Projections (HMMA bf16x3)
    gemm_wmma_bf16x3<<<dim3(NQ / 128,   S_LEN / 128), 256, GEMM_SMEM_BYTES>>>(xh, xl, wqTh, wqTl, q, NQ,   HID);
    gemm_wmma_bf16x3<<<dim3(NKVD / 128, S_LEN / 128), 256, GEMM_SMEM_BYTES>>>(xh, xl, wkTh, wkTl, k, NKVD, HID);
    gemm_wmma_bf16x3<<<dim3(NKVD / 128, S_LEN / 128), 256, GEMM_SMEM_BYTES>>>(xh, xl, wvTh, wvTl, v, NKVD, HID);

    // RMSNorm + RoPE
    rmsnorm_rope<<<S_LEN * NH,  128>>>(q, qn, cs, sn, NH);
    rmsnorm_rope<<<S_LEN * NKV, 128>>>(k, kn, cs, sn, NKV);

    // Causal GQA flash attention (fp32)
    flash_attn<<<dim3(NH, S_LEN / 32), 128>>>(q, k, v, attn);

    // Output projection
    split_bf16<<<(S_LEN * NQ + 255) / 256, 256>>>(attn, ath, atl, S_LEN * NQ);
    gemm_wmma_bf16x3<<<dim3(HID / 128, S_LEN / 128), 256, GEMM_SMEM_BYTES>>>(ath, atl, woTh, woTl, out, HID, NQ);
}

// round 4
// speedup vs baseline: 3.2087x; 1.3435x over previous
#include <cuda_runtime.h>
#include <cuda_bf16.h>
#include <cuda_fp16.h>
#include <mma.h>
#include <cstdint>
#include <math.h>

using namespace nvcuda;

#define S_LEN 2048
#define HID   2048
#define NH    32
#define NKV   4
#define HD    128
#define NQ    (NH * HD)    // 4096
#define NKVD  (NKV * HD)   // 512

// ---------------------------------------------------------------------------
// Scratch (device globals — no allocation allowed)
// ---------------------------------------------------------------------------
__device__ float g_q[S_LEN * NQ];
__device__ float g_k[S_LEN * NKVD];
__device__ float g_v[S_LEN * NKVD];

__device__ __nv_bfloat16 g_xh[S_LEN * HID];
__device__ __nv_bfloat16 g_xl[S_LEN * HID];
__device__ __nv_bfloat16 g_wqTh[NQ * HID];
__device__ __nv_bfloat16 g_wqTl[NQ * HID];
__device__ __nv_bfloat16 g_wkTh[NKVD * HID];
__device__ __nv_bfloat16 g_wkTl[NKVD * HID];
__device__ __nv_bfloat16 g_wvTh[NKVD * HID];
__device__ __nv_bfloat16 g_wvTl[NKVD * HID];
__device__ __nv_bfloat16 g_woTh[HID * NQ];
__device__ __nv_bfloat16 g_woTl[HID * NQ];
__device__ __nv_bfloat16 g_ath[S_LEN * NQ];
__device__ __nv_bfloat16 g_atl[S_LEN * NQ];

__device__ __half g_q16h[S_LEN * NQ];
__device__ __half g_q16l[S_LEN * NQ];
__device__ __half g_k16h[S_LEN * NKVD];
__device__ __half g_k16l[S_LEN * NKVD];
__device__ __half g_v16[S_LEN * NKVD];

// ---------------------------------------------------------------------------
// helpers
// ---------------------------------------------------------------------------
__device__ __forceinline__ uint32_t smem_u32(const void* p) {
    uint32_t a;
    asm("{ .reg .u64 t; cvta.to.shared.u64 t, %1; cvt.u32.u64 %0, t; }"
        : "=r"(a) : "l"(p));
    return a;
}

__device__ __forceinline__ void cpa16(uint32_t dst, const void* src) {
    asm volatile(
        "{\n\t.reg .u64 g;\n\tcvta.to.global.u64 g, %1;\n\t"
        "cp.async.cg.shared.global [%0], [g], 16;\n\t}"
        :: "r"(dst), "l"(src) : "memory");
}
#define CPA_COMMIT() asm volatile("cp.async.commit_group;" ::: "memory")
#define CPA_WAIT1()  asm volatile("cp.async.wait_group 1;" ::: "memory")
#define CPA_WAIT0()  asm volatile("cp.async.wait_group 0;" ::: "memory")

// Fast exp on the FFMA pipe (no MUFU). Valid for x <= ~0; clamped at -87.
// Rel err < 3e-6 on [-87, 0].
__device__ __forceinline__ float fexp(float x) {
    x = fmaxf(x, -87.0f);
    float z  = fmaf(x, 1.44269504089f, 12582912.0f);   // round(x*log2e) in low bits
    float nf = z - 12582912.0f;
    float f  = fmaf(x, 1.44269504089f, -nf);           // frac in [-0.5, 0.5]
    float p  = 1.333355815e-3f;
    p = fmaf(p, f, 9.618129107e-3f);
    p = fmaf(p, f, 5.550410866e-2f);
    p = fmaf(p, f, 2.402265069e-1f);
    p = fmaf(p, f, 6.931471806e-1f);
    p = fmaf(p, f, 1.0f);
    int n = __float_as_int(z) - 0x4B400000;            // integer part
    return __int_as_float(__float_as_int(p) + (n << 23));
}

// ---------------------------------------------------------------------------
// fp32 -> bf16 hi/lo split (elementwise)
// ---------------------------------------------------------------------------
__global__ void split_bf16(const float* __restrict__ in,
                           __nv_bfloat16* __restrict__ oh,
                           __nv_bfloat16* __restrict__ ol, int n)
{
    int i = blockIdx.x * blockDim.x + threadIdx.x;
    if (i < n) {
        float x = in[i];
        __nv_bfloat16 h = __float2bfloat16(x);
        oh[i] = h;
        ol[i] = __float2bfloat16(x - __bfloat162float(h));
    }
}

__global__ void cvt_f16(const float* __restrict__ in, __half* __restrict__ out, int n)
{
    int i = blockIdx.x * blockDim.x + threadIdx.x;
    if (i < n) out[i] = __float2half(in[i]);
}

// ---------------------------------------------------------------------------
// Transpose [R][C] fp32 -> [C][R] bf16 hi/lo
// ---------------------------------------------------------------------------
__global__ void transpose_split(const float* __restrict__ in,
                                __nv_bfloat16* __restrict__ oh,
                                __nv_bfloat16* __restrict__ ol, int R, int C)
{
    __shared__ float t[32][33];
    int c0 = blockIdx.x << 5, r0 = blockIdx.y << 5;
    int x = threadIdx.x, y = threadIdx.y;
#pragma unroll
    for (int j = y; j < 32; j += 8)
        t[j][x] = in[(size_t)(r0 + j) * C + c0 + x];
    __syncthreads();
#pragma unroll
    for (int j = y; j < 32; j += 8) {
        float v = t[x][j];
        __nv_bfloat16 h = __float2bfloat16(v);
        size_t o = (size_t)(c0 + j) * R + r0 + x;
        oh[o] = h;
        ol[o] = __float2bfloat16(v - __bfloat162float(h));
    }
}

// ---------------------------------------------------------------------------
// bf16x3 wmma GEMM (unchanged from R3 passing version)
// ---------------------------------------------------------------------------
#define GBK    32
#define GPAD   40
#define GTILE  (128 * GPAD)
#define GSTAGE (4 * GTILE)
#define GEMM_SMEM_BYTES (2 * GSTAGE * 2)

__global__ void __launch_bounds__(256) gemm_wmma_bf16x3(
    const __nv_bfloat16* __restrict__ Ah, const __nv_bfloat16* __restrict__ Al,
    const __nv_bfloat16* __restrict__ Bh, const __nv_bfloat16* __restrict__ Bl,
    float* __restrict__ C, int N, int K)
{
    extern __shared__ __nv_bfloat16 sm[];
    const int tid = threadIdx.x;
    const int wid = tid >> 5;
    const int m0 = blockIdx.y << 7, n0 = blockIdx.x << 7;
    const int wm = wid >> 1;
    const int wn = wid & 1;

    wmma::fragment<wmma::accumulator, 16, 16, 16, float> acc[2][4];
#pragma unroll
    for (int i = 0; i < 2; i++)
#pragma unroll
        for (int j = 0; j < 4; j++)
            wmma::fill_fragment(acc[i][j], 0.0f);

    const int lrow = tid >> 1;
    const int cb   = (tid & 1) * 2;

    const __nv_bfloat16* gbase[4] = {Ah, Al, Bh, Bl};
    const int grow0[4] = {m0, m0, n0, n0};

    const int nck = K / GBK;

    auto load_stage = [&](int ck, int s) {
        const int k0 = ck * GBK;
#pragma unroll
        for (int t = 0; t < 4; t++) {
            uint32_t dst = smem_u32(sm + s * GSTAGE + t * GTILE) + lrow * (GPAD * 2);
            const __nv_bfloat16* src = gbase[t] + (size_t)(grow0[t] + lrow) * K + k0;
            cpa16(dst + (cb + 0) * 16, src + (cb + 0) * 8);
            cpa16(dst + (cb + 1) * 16, src + (cb + 1) * 8);
        }
        CPA_COMMIT();
    };

    load_stage(0, 0);

    for (int ck = 0; ck < nck; ck++) {
        if (ck + 1 < nck) {
            load_stage(ck + 1, (ck + 1) & 1);
            CPA_WAIT1();
        } else {
            CPA_WAIT0();
        }
        __syncthreads();

        const int s = ck & 1;
        const __nv_bfloat16* pAh = sm + s * GSTAGE + 0 * GTILE + wm * 32 * GPAD;
        const __nv_bfloat16* pAl = sm + s * GSTAGE + 1 * GTILE + wm * 32 * GPAD;
        const __nv_bfloat16* pBh = sm + s * GSTAGE + 2 * GTILE + wn * 64 * GPAD;
        const __nv_bfloat16* pBl = sm + s * GSTAGE + 3 * GTILE + wn * 64 * GPAD;

#pragma unroll
        for (int kk = 0; kk < GBK; kk += 16) {
            wmma::fragment<wmma::matrix_a, 16, 16, 16, __nv_bfloat16, wmma::row_major> ah[2], al[2];
            wmma::fragment<wmma::matrix_b, 16, 16, 16, __nv_bfloat16, wmma::col_major> bh[4], bl[4];
#pragma unroll
            for (int i = 0; i < 2; i++) {
                wmma::load_matrix_sync(ah[i], pAh + i * 16 * GPAD + kk, GPAD);
                wmma::load_matrix_sync(al[i], pAl + i * 16 * GPAD + kk, GPAD);
            }
#pragma unroll
            for (int j = 0; j < 4; j++) {
                wmma::load_matrix_sync(bh[j], pBh + j * 16 * GPAD + kk, GPAD);
                wmma::load_matrix_sync(bl[j], pBl + j * 16 * GPAD + kk, GPAD);
            }
#pragma unroll
            for (int i = 0; i < 2; i++)
#pragma unroll
                for (int j = 0; j < 4; j++) {
                    wmma::mma_sync(acc[i][j], ah[i], bh[j], acc[i][j]);
                    wmma::mma_sync(acc[i][j], ah[i], bl[j], acc[i][j]);
                    wmma::mma_sync(acc[i][j], al[i], bh[j], acc[i][j]);
                }
        }
        __syncthreads();
    }

#pragma unroll
    for (int i = 0; i < 2; i++)
#pragma unroll
        for (int j = 0; j < 4; j++) {
            float* cp = C + (size_t)(m0 + wm * 32 + i * 16) * N + n0 + wn * 64 + j * 16;
            wmma::store_matrix_sync(cp, acc[i][j], N, wmma::mem_row_major);
        }
}

// ---------------------------------------------------------------------------
// Fused RMSNorm + RoPE -> fp16 hi/lo output
// ---------------------------------------------------------------------------
__global__ __launch_bounds__(128) void rmsnorm_rope_f16(
    const float* __restrict__ x, const float* __restrict__ w,
    const float* __restrict__ cs, const float* __restrict__ sn, int heads,
    __half* __restrict__ oh, __half* __restrict__ ol)
{
    const int b = blockIdx.x;
    const int s = b / heads;
    const int h = b - s * heads;
    const int d = threadIdx.x;

    const size_t ro = ((size_t)s * heads + h) * HD;
    float v = x[ro + d];

    float ssq = v * v;
#pragma unroll
    for (int off = 16; off > 0; off >>= 1)
        ssq += __shfl_xor_sync(0xffffffffu, ssq, off);

    __shared__ float red[4];
    __shared__ float sh[HD];
    if ((d & 31) == 0) red[d >> 5] = ssq;
    __syncthreads();
    float tot = red[0] + red[1] + red[2] + red[3];

    float xn = v * rsqrtf(tot * (1.0f / HD) + 1e-6f) * w[d];
    sh[d] = xn;
    __syncthreads();

    float partner = (d < 64) ? -sh[d + 64] : sh[d - 64];
    float res = xn * cs[s * HD + d] + partner * sn[s * HD + d];

    __half h16 = __float2half(res);
    oh[ro + d] = h16;
    ol[ro + d] = __float2half(res - __half2float(h16));
}

// ---------------------------------------------------------------------------
// Tensor-core flash attention.
// CTA = (q-head, 64-query tile). 256 threads (8 warps).
// QK: fp16 hi/lo split (3-term exact-ish). P,V: fp16 single. O: fp32 smem.
// Epilogue writes bf16 hi/lo directly for the output projection.
// ---------------------------------------------------------------------------
#define QLD 136      // fp16 row stride, elements
#define SLD 132      // fp32 score/PV row stride
#define PLD 72       // fp16 P row stride

#define OFF_QH 0
#define OFF_QL 17408
#define OFF_KH 34816
#define OFF_KL 52224
#define OFF_V  69632
#define OFF_S  87040
#define OFF_P  120832
#define OFF_O  130048
#define OFF_M  162816
#define OFF_L  163072
#define OFF_AL 163328
#define FLASH_SMEM 163584

__global__ void __launch_bounds__(256) flash_wmma(
    const __half* __restrict__ qh, const __half* __restrict__ ql,
    const __half* __restrict__ kh, const __half* __restrict__ kl,
    const __half* __restrict__ vv,
    __nv_bfloat16* __restrict__ oh, __nv_bfloat16* __restrict__ ol)
{
    extern __shared__ char smc[];
    __half* sQh = (__half*)(smc + OFF_QH);
    __half* sQl = (__half*)(smc + OFF_QL);
    __half* sKh = (__half*)(smc + OFF_KH);
    __half* sKl = (__half*)(smc + OFF_KL);
    __half* sV  = (__half*)(smc + OFF_V);
    float*  sS  = (float*)(smc + OFF_S);
    __half* sP  = (__half*)(smc + OFF_P);
    float*  sO  = (float*)(smc + OFF_O);
    float*  sM  = (float*)(smc + OFF_M);
    float*  sL  = (float*)(smc + OFF_L);
    float*  sA  = (float*)(smc + OFF_AL);

    const int h     = blockIdx.x;
    const int ptile = (int)gridDim.y - 1 - blockIdx.y;  // long CTAs first
    const int m0    = ptile << 6;
    const int kvh   = h >> 3;
    const int tid   = threadIdx.x;
    const int wid   = tid >> 5;
    const int rs    = wid >> 1;      // row slab 0..3 (16 rows each)
    const int ch    = wid & 1;       // col half
    const float scale = 0.08838834764831845f;   // 1/sqrt(128)

    // Load Q tile (hi & lo)
    {
        uint32_t dqh = smem_u32(sQh), dql = smem_u32(sQl);
#pragma unroll
        for (int i = 0; i < 4; i++) {
            int idx = tid + (i << 8);
            int r = idx >> 4, c = idx & 15;
            size_t so = (size_t)(m0 + r) * NQ + h * HD + (c << 3);
            uint32_t off = r * (QLD * 2) + (c << 4);
            cpa16(dqh + off, qh + so);
            cpa16(dql + off, ql + so);
        }
        CPA_COMMIT();
    }
    // Init O, m, l
    for (int i = tid; i < 64 * 128 / 4; i += 256)
        ((float4*)sO)[i] = make_float4(0.f, 0.f, 0.f, 0.f);
    if (tid < 64) { sM[tid] = -1e30f; sL[tid] = 0.f; }
    CPA_WAIT0();
    __syncthreads();

    for (int kb = 0; kb <= ptile; kb++) {
        const int k0g = kb << 6;

        // Load K (hi/lo) and V tiles
        {
            uint32_t dkh = smem_u32(sKh), dkl = smem_u32(sKl), dv = smem_u32(sV);
#pragma unroll
            for (int i = 0; i < 4; i++) {
                int idx = tid + (i << 8);
                int r = idx >> 4, c = idx & 15;
                size_t so = (size_t)(k0g + r) * NKVD + kvh * HD + (c << 3);
                uint32_t off = r * (QLD * 2) + (c << 4);
                cpa16(dkh + off, kh + so);
                cpa16(dkl + off, kl + so);
                cpa16(dv + off,  vv + so);
            }
            CPA_COMMIT();
            CPA_WAIT0();
        }
        __syncthreads();

        // --- QK^T ---
        {
            wmma::fragment<wmma::accumulator, 16, 16, 16, float> accS[2];
            wmma::fill_fragment(accS[0], 0.0f);
            wmma::fill_fragment(accS[1], 0.0f);
#pragma unroll
            for (int k0 = 0; k0 < 128; k0 += 16) {
                wmma::fragment<wmma::matrix_a, 16, 16, 16, __half, wmma::row_major> ah, al;
                wmma::load_matrix_sync(ah, sQh + rs * 16 * QLD + k0, QLD);
                wmma::load_matrix_sync(al, sQl + rs * 16 * QLD + k0, QLD);
#pragma unroll
                for (int j = 0; j < 2; j++) {
                    wmma::fragment<wmma::matrix_b, 16, 16, 16, __half, wmma::col_major> bh, bl;
                    int kcol = ch * 32 + j * 16;
                    wmma::load_matrix_sync(bh, sKh + kcol * QLD + k0, QLD);
                    wmma::load_matrix_sync(bl, sKl + kcol * QLD + k0, QLD);
                    wmma::mma_sync(accS[j], ah, bh, accS[j]);
                    wmma::mma_sync(accS[j], ah, bl, accS[j]);
                    wmma::mma_sync(accS[j], al, bh, accS[j]);
                }
            }
#pragma unroll
            for (int j = 0; j < 2; j++)
                wmma::store_matrix_sync(sS + rs * 16 * SLD + ch * 32 + j * 16,
                                        accS[j], SLD, wmma::mem_row_major);
        }
        __syncthreads();

        // --- online softmax (FFMA-pipe exp) ---
        {
            const int r  = tid >> 2;
            const int q4 = tid & 3;
            float* srow = sS + r * SLD + q4 * 16;
            const int qglob = m0 + r;
            const int kbase = k0g + q4 * 16;

            float vals[16];
            float mx = -1e30f;
#pragma unroll
            for (int j = 0; j < 16; j++) {
                float s = srow[j];
                s = (kbase + j <= qglob) ? s * scale : -1e30f;
                vals[j] = s;
                mx = fmaxf(mx, s);
            }
            mx = fmaxf(mx, __shfl_xor_sync(0xffffffffu, mx, 1));
            mx = fmaxf(mx, __shfl_xor_sync(0xffffffffu, mx, 2));

            float mold = sM[r];
            float mnew = fmaxf(mold, mx);
            float alpha = fexp(mold - mnew);

            __half* prow = sP + r * PLD + q4 * 16;
            float lsum = 0.f;
#pragma unroll
            for (int j = 0; j < 16; j++) {
                float p = fexp(vals[j] - mnew);
                prow[j] = __float2half(p);
                lsum += p;
            }
            lsum += __shfl_xor_sync(0xffffffffu, lsum, 1);
            lsum += __shfl_xor_sync(0xffffffffu, lsum, 2);

            if (q4 == 0) {
                sM[r] = mnew;
                sL[r] = sL[r] * alpha + lsum;
                sA[r] = alpha;
            }
        }
        __syncthreads();

        // --- P @ V ---
        {
            wmma::fragment<wmma::accumulator, 16, 16, 16, float> accO[4];
#pragma unroll
            for (int j = 0; j < 4; j++) wmma::fill_fragment(accO[j], 0.0f);
#pragma unroll
            for (int k0 = 0; k0 < 64; k0 += 16) {
                wmma::fragment<wmma::matrix_a, 16, 16, 16, __half, wmma::row_major> a;
                wmma::load_matrix_sync(a, sP + rs * 16 * PLD + k0, PLD);
#pragma unroll
                for (int j = 0; j < 4; j++) {
                    wmma::fragment<wmma::matrix_b, 16, 16, 16, __half, wmma::row_major> b;
                    wmma::load_matrix_sync(b, sV + k0 * QLD + ch * 64 + j * 16, QLD);
                    wmma::mma_sync(accO[j], a, b, accO[j]);
                }
            }
#pragma unroll
            for (int j = 0; j < 4; j++)
                wmma::store_matrix_sync(sS + rs * 16 * SLD + ch * 64 + j * 16,
                                        accO[j], SLD, wmma::mem_row_major);
        }
        __syncthreads();

        // --- O = O*alpha + PV ---
        {
            const int r  = tid >> 2;
            const int c0 = (tid & 3) << 5;
            const float a = sA[r];
            float4* op = (float4*)(sO + r * 128 + c0);
            const float4* pv = (const float4*)(sS + r * SLD + c0);
#pragma unroll
            for (int j = 0; j < 8; j++) {
                float4 o = op[j], p = pv[j];
                o.x = o.x * a + p.x;
                o.y = o.y * a + p.y;
                o.z = o.z * a + p.z;
                o.w = o.w * a + p.w;
                op[j] = o;
            }
        }
        __syncthreads();
    }

    // Epilogue: normalize, write bf16 hi/lo
    {
        const int r  = tid >> 2;
        const int c0 = (tid & 3) << 5;
        const float inv = 1.0f / sL[r];
        const size_t base = (size_t)(m0 + r) * NQ + h * HD + c0;
#pragma unroll
        for (int j = 0; j < 32; j++) {
            float o = sO[r * 128 + c0 + j] * inv;
            __nv_bfloat16 hi = __float2bfloat16(o);
            oh[base + j] = hi;
            ol[base + j] = __float2bfloat16(o - __bfloat162float(hi));
        }
    }
}

// ---------------------------------------------------------------------------
extern "C" void kernel_launch(void* const* d_in, const int* in_sizes, int n_in,
                              void* d_out, int out_size)
{
    (void)in_sizes; (void)n_in; (void)out_size;
    const float* x  = (const float*)d_in[0];
    const float* wq = (const float*)d_in[1];
    const float* wk = (const float*)d_in[2];
    const float* wv = (const float*)d_in[3];
    const float* wo = (const float*)d_in[4];
    const float* qn = (const float*)d_in[5];
    const float* kn = (const float*)d_in[6];
    const float* cs = (const float*)d_in[7];
    const float* sn = (const float*)d_in[8];
    float* out = (float*)d_out;

    float *q, *k, *v;
    cudaGetSymbolAddress((void**)&q, g_q);
    cudaGetSymbolAddress((void**)&k, g_k);
    cudaGetSymbolAddress((void**)&v, g_v);

    __nv_bfloat16 *xh, *xl, *wqTh, *wqTl, *wkTh, *wkTl, *wvTh, *wvTl, *woTh, *woTl, *ath, *atl;
    cudaGetSymbolAddress((void**)&xh,   g_xh);
    cudaGetSymbolAddress((void**)&xl,   g_xl);
    cudaGetSymbolAddress((void**)&wqTh, g_wqTh);
    cudaGetSymbolAddress((void**)&wqTl, g_wqTl);
    cudaGetSymbolAddress((void**)&wkTh, g_wkTh);
    cudaGetSymbolAddress((void**)&wkTl, g_wkTl);
    cudaGetSymbolAddress((void**)&wvTh, g_wvTh);
    cudaGetSymbolAddress((void**)&wvTl, g_wvTl);
    cudaGetSymbolAddress((void**)&woTh, g_woTh);
    cudaGetSymbolAddress((void**)&woTl, g_woTl);
    cudaGetSymbolAddress((void**)&ath,  g_ath);
    cudaGetSymbolAddress((void**)&atl,  g_atl);

    __half *q16h, *q16l, *k16h, *k16l, *v16;
    cudaGetSymbolAddress((void**)&q16h, g_q16h);
    cudaGetSymbolAddress((void**)&q16l, g_q16l);
    cudaGetSymbolAddress((void**)&k16h, g_k16h);
    cudaGetSymbolAddress((void**)&k16l, g_k16l);
    cudaGetSymbolAddress((void**)&v16,  g_v16);

    cudaFuncSetAttribute(gemm_wmma_bf16x3,
                         cudaFuncAttributeMaxDynamicSharedMemorySize, GEMM_SMEM_BYTES);
    cudaFuncSetAttribute(flash_wmma,
                         cudaFuncAttributeMaxDynamicSharedMemorySize, FLASH_SMEM);

    // Split activations; transpose+split weights to [N][K] bf16
    split_bf16<<<(S_LEN * HID + 255) / 256, 256>>>(x, xh, xl, S_LEN * HID);
    transpose_split<<<dim3(NQ / 32,   HID / 32), dim3(32, 8)>>>(wq, wqTh, wqTl, HID, NQ);
    transpose_split<<<dim3(NKVD / 32, HID / 32), dim3(32, 8)>>>(wk, wkTh, wkTl, HID, NKVD);
    transpose_split<<<dim3(NKVD / 32, HID / 32), dim3(32, 8)>>>(wv, wvTh, wvTl, HID, NKVD);
    transpose_split<<<dim3(HID / 32,  NQ / 32),  dim3(32, 8)>>>(wo, woTh, woTl, NQ, HID);

    // Projections (HMMA bf16x3)
    gemm_wmma_bf16x3<<<dim3(NQ / 128,   S_LEN / 128), 256, GEMM_SMEM_BYTES>>>(xh, xl, wqTh, wqTl, q, NQ,   HID);
    gemm_wmma_bf16x3<<<dim3(NKVD / 128, S_LEN / 128), 256, GEMM_SMEM_BYTES>>>(xh, xl, wkTh, wkTl, k, NKVD, HID);
    gemm_wmma_bf16x3<<<dim3(NKVD / 128, S_LEN / 128), 256, GEMM_SMEM_BYTES>>>(xh, xl, wvTh, wvTl, v, NKVD, HID);

    // RMSNorm + RoPE -> fp16 hi/lo; V -> fp16
    rmsnorm_rope_f16<<<S_LEN * NH,  128>>>(q, qn, cs, sn, NH,  q16h, q16l);
    rmsnorm_rope_f16<<<S_LEN * NKV, 128>>>(k, kn, cs, sn, NKV, k16h, k16l);
    cvt_f16<<<(S_LEN * NKVD + 255) / 256, 256>>>(v, v16, S_LEN * NKVD);

    // Tensor-core causal GQA flash attention -> bf16 hi/lo
    flash_wmma<<<dim3(NH, S_LEN / 64), 256, FLASH_SMEM>>>(
        q16h, q16l, k16h, k16l, v16, ath, atl);

    // Output projection
    gemm_wmma_bf16x3<<<dim3(HID / 128, S_LEN / 128), 256, GEMM_SMEM_BYTES>>>(ath, atl, woTh, woTl, out, HID, NQ);
}

// round 5
// speedup vs baseline: 3.6106x; 1.1253x over previous
#include <cuda_runtime.h>
#include <cuda_bf16.h>
#include <cuda_fp16.h>
#include <cstdint>
#include <math.h>

#define S_LEN 2048
#define HID   2048
#define NH    32
#define NKV   4
#define HD    128
#define NQ    (NH * HD)    // 4096
#define NKVD  (NKV * HD)   // 512
#define NQKV  (NQ + 2 * NKVD)  // 5120

// ---------------------------------------------------------------------------
// Scratch (device globals — no allocation allowed)
// ---------------------------------------------------------------------------
__device__ float g_qkv[S_LEN * NQKV];          // fused QKV output (40 MB)

__device__ __nv_bfloat16 g_xh[S_LEN * HID];
__device__ __nv_bfloat16 g_xl[S_LEN * HID];
__device__ __nv_bfloat16 g_wqkvTh[NQKV * HID]; // [5120][2048]
__device__ __nv_bfloat16 g_wqkvTl[NQKV * HID];
__device__ __nv_bfloat16 g_woTh[HID * NQ];
__device__ __nv_bfloat16 g_woTl[HID * NQ];
__device__ __nv_bfloat16 g_ath[S_LEN * NQ];
__device__ __nv_bfloat16 g_atl[S_LEN * NQ];

__device__ __half g_q16h[S_LEN * NQ];
__device__ __half g_q16l[S_LEN * NQ];
__device__ __half g_k16h[S_LEN * NKVD];
__device__ __half g_k16l[S_LEN * NKVD];
__device__ __half g_v16[S_LEN * NKVD];

// ---------------------------------------------------------------------------
// helpers
// ---------------------------------------------------------------------------
__device__ __forceinline__ uint32_t smem_u32(const void* p) {
    uint32_t a;
    asm("{ .reg .u64 t; cvta.to.shared.u64 t, %1; cvt.u32.u64 %0, t; }"
        : "=r"(a) : "l"(p));
    return a;
}

__device__ __forceinline__ void cpa16(uint32_t dst, const void* src) {
    asm volatile(
        "{\n\t.reg .u64 g;\n\tcvta.to.global.u64 g, %1;\n\t"
        "cp.async.cg.shared.global [%0], [g], 16;\n\t}"
        :: "r"(dst), "l"(src) : "memory");
}
#define CPA_COMMIT() asm volatile("cp.async.commit_group;" ::: "memory")
#define CPA_WAIT1()  asm volatile("cp.async.wait_group 1;" ::: "memory")
#define CPA_WAIT0()  asm volatile("cp.async.wait_group 0;" ::: "memory")

#define LDSM4(r, addr) \
    asm volatile("ldmatrix.sync.aligned.m8n8.x4.shared.b16 {%0,%1,%2,%3}, [%4];" \
        : "=r"((r)[0]), "=r"((r)[1]), "=r"((r)[2]), "=r"((r)[3]) : "r"(addr))

__device__ __forceinline__ void mma16816(float* d, const uint32_t* a,
                                         uint32_t b0, uint32_t b1) {
    asm volatile(
        "mma.sync.aligned.m16n8k16.row.col.f32.bf16.bf16.f32 "
        "{%0,%1,%2,%3}, {%4,%5,%6,%7}, {%8,%9}, {%0,%1,%2,%3};"
        : "+f"(d[0]), "+f"(d[1]), "+f"(d[2]), "+f"(d[3])
        : "r"(a[0]), "r"(a[1]), "r"(a[2]), "r"(a[3]), "r"(b0), "r"(b1));
}

// Fast exp on the FFMA pipe. Rel err < 3e-6 on [-87, 0].
__device__ __forceinline__ float fexp(float x) {
    x = fmaxf(x, -87.0f);
    float z  = fmaf(x, 1.44269504089f, 12582912.0f);
    float nf = z - 12582912.0f;
    float f  = fmaf(x, 1.44269504089f, -nf);
    float p  = 1.333355815e-3f;
    p = fmaf(p, f, 9.618129107e-3f);
    p = fmaf(p, f, 5.550410866e-2f);
    p = fmaf(p, f, 2.402265069e-1f);
    p = fmaf(p, f, 6.931471806e-1f);
    p = fmaf(p, f, 1.0f);
    int n = __float_as_int(z) - 0x4B400000;
    return __int_as_float(__float_as_int(p) + (n << 23));
}

// ---------------------------------------------------------------------------
// fp32 -> bf16 hi/lo split
// ---------------------------------------------------------------------------
__global__ void split_bf16(const float* __restrict__ in,
                           __nv_bfloat16* __restrict__ oh,
                           __nv_bfloat16* __restrict__ ol, int n)
{
    int i = blockIdx.x * blockDim.x + threadIdx.x;
    if (i < n) {
        float x = in[i];
        __nv_bfloat16 h = __float2bfloat16(x);
        oh[i] = h;
        ol[i] = __float2bfloat16(x - __bfloat162float(h));
    }
}

// v slice of fused qkv -> fp16
__global__ void cvt_v16(const float* __restrict__ qkv, __half* __restrict__ out)
{
    int i = blockIdx.x * blockDim.x + threadIdx.x;   // 0 .. S*NKVD
    int s = i >> 9, d = i & 511;
    out[i] = __float2half(qkv[(size_t)s * NQKV + NQ + NKVD + d]);
}

// ---------------------------------------------------------------------------
// Transpose [R][C] fp32 -> [C][R] bf16 hi/lo
// ---------------------------------------------------------------------------
__global__ void transpose_split(const float* __restrict__ in,
                                __nv_bfloat16* __restrict__ oh,
                                __nv_bfloat16* __restrict__ ol, int R, int C)
{
    __shared__ float t[32][33];
    int c0 = blockIdx.x << 5, r0 = blockIdx.y << 5;
    int x = threadIdx.x, y = threadIdx.y;
#pragma unroll
    for (int j = y; j < 32; j += 8)
        t[j][x] = in[(size_t)(r0 + j) * C + c0 + x];
    __syncthreads();
#pragma unroll
    for (int j = y; j < 32; j += 8) {
        float v = t[x][j];
        __nv_bfloat16 h = __float2bfloat16(v);
        size_t o = (size_t)(c0 + j) * R + r0 + x;
        oh[o] = h;
        ol[o] = __float2bfloat16(v - __bfloat162float(h));
    }
}

// ---------------------------------------------------------------------------
// Raw-HMMA bf16x3 GEMM: C[m][n] = sum_k A[m][k] * BT[n][k]
// CTA 128x128, 8 warps, warp tile 64x32. K chunks of 64, 2-stage cp.async.
// Smem rows padded to 144 B (conflict-free ldmatrix, stride 36 words).
// ---------------------------------------------------------------------------
#define TPAD_B 144                       // bytes per smem row
#define TILE_B (128 * TPAD_B)            // 18432
#define STG_B  (4 * TILE_B)              // Ah, Al, Bh, Bl = 73728
#define GEMM_SMEM (2 * STG_B)            // 147456

__global__ void __launch_bounds__(256) gemm_mma_bf16x3(
    const __nv_bfloat16* __restrict__ Ah, const __nv_bfloat16* __restrict__ Al,
    const __nv_bfloat16* __restrict__ Bh, const __nv_bfloat16* __restrict__ Bl,
    float* __restrict__ C, int N, int K)
{
    extern __shared__ char smraw[];
    const int tid  = threadIdx.x;
    const int wid  = tid >> 5, lane = tid & 31;
    const int m0 = blockIdx.y << 7, n0 = blockIdx.x << 7;
    const int wm = wid >> 2;             // 0..1  (64-row slab)
    const int wn = wid & 3;              // 0..3  (32-col slab)

    const uint32_t sbase = smem_u32(smraw);

    float acc[4][4][4];
#pragma unroll
    for (int i = 0; i < 4; i++)
#pragma unroll
        for (int j = 0; j < 4; j++)
#pragma unroll
            for (int r = 0; r < 4; r++) acc[i][j][r] = 0.0f;

    // ldmatrix lane addressing: row = lane&15, k-halfword offset = (lane>>4)*8
    const uint32_t lrow = lane & 15;
    const uint32_t lkof = (lane >> 4) << 4;   // bytes

    const __nv_bfloat16* gb[4] = {Ah, Al, Bh, Bl};
    const int gr0[4] = {m0, m0, n0, n0};
    const int nck = K >> 6;

    auto load_stage = [&](int ck, int s) {
        const int k0 = ck << 6;
        const uint32_t sb = sbase + s * STG_B;
#pragma unroll
        for (int t = 0; t < 4; t++) {
#pragma unroll
            for (int i = 0; i < 4; i++) {
                int idx = (i << 8) + tid;          // 0..1023
                int row = idx >> 3, c = idx & 7;
                cpa16(sb + t * TILE_B + row * TPAD_B + c * 16,
                      gb[t] + (size_t)(gr0[t] + row) * K + k0 + c * 8);
            }
        }
        CPA_COMMIT();
    };

    load_stage(0, 0);

    for (int ck = 0; ck < nck; ck++) {
        if (ck + 1 < nck) { load_stage(ck + 1, (ck + 1) & 1); CPA_WAIT1(); }
        else             { CPA_WAIT0(); }
        __syncthreads();

        const uint32_t sb = sbase + (ck & 1) * STG_B;
        const uint32_t aHb = sb + (wm * 64 + lrow) * TPAD_B + lkof;
        const uint32_t aLb = aHb + TILE_B;
        const uint32_t bHb = sb + 2 * TILE_B + (wn * 32 + lrow) * TPAD_B + lkof;
        const uint32_t bLb = bHb + TILE_B;

#pragma unroll
        for (int kk = 0; kk < 4; kk++) {
            const uint32_t ko = kk * 32;      // 16 halves = 32 B
            uint32_t ah[4][4], al[4][4], bh[2][4], bl[2][4];
#pragma unroll
            for (int mt = 0; mt < 4; mt++) {
                LDSM4(ah[mt], aHb + mt * 16 * TPAD_B + ko);
                LDSM4(al[mt], aLb + mt * 16 * TPAD_B + ko);
            }
#pragma unroll
            for (int np = 0; np < 2; np++) {
                LDSM4(bh[np], bHb + np * 16 * TPAD_B + ko);
                LDSM4(bl[np], bLb + np * 16 * TPAD_B + ko);
            }
#pragma unroll
            for (int mt = 0; mt < 4; mt++) {
#pragma unroll
                for (int nt = 0; nt < 4; nt++) {
                    const int np = nt >> 1, sl = nt & 1;
                    mma16816(acc[mt][nt], ah[mt], bh[np][sl], bh[np][sl + 2]);
                    mma16816(acc[mt][nt], ah[mt], bl[np][sl], bl[np][sl + 2]);
                    mma16816(acc[mt][nt], al[mt], bh[np][sl], bh[np][sl + 2]);
                }
            }
        }
        __syncthreads();
    }

    // Epilogue: direct fp32 stores (float2)
    const int erow = (lane >> 2);
    const int ecol = (lane & 3) << 1;
#pragma unroll
    for (int mt = 0; mt < 4; mt++) {
#pragma unroll
        for (int nt = 0; nt < 4; nt++) {
            const int r = m0 + wm * 64 + mt * 16 + erow;
            const int c = n0 + wn * 32 + nt * 8 + ecol;
            *(float2*)(C + (size_t)r * N + c) =
                make_float2(acc[mt][nt][0], acc[mt][nt][1]);
            *(float2*)(C + (size_t)(r + 8) * N + c) =
                make_float2(acc[mt][nt][2], acc[mt][nt][3]);
        }
    }
}

// ---------------------------------------------------------------------------
// Fused RMSNorm + RoPE, reading a column slice of fused qkv -> fp16 hi/lo
// ---------------------------------------------------------------------------
__global__ __launch_bounds__(128) void rmsnorm_rope_f16(
    const float* __restrict__ qkv, int colOff, const float* __restrict__ w,
    const float* __restrict__ cs, const float* __restrict__ sn, int heads,
    __half* __restrict__ oh, __half* __restrict__ ol)
{
    const int b = blockIdx.x;
    const int s = b / heads;
    const int h = b - s * heads;
    const int d = threadIdx.x;

    const size_t io = (size_t)s * NQKV + colOff + h * HD;
    const size_t oo = ((size_t)s * heads + h) * HD;
    float v = qkv[io + d];

    float ssq = v * v;
#pragma unroll
    for (int off = 16; off > 0; off >>= 1)
        ssq += __shfl_xor_sync(0xffffffffu, ssq, off);

    __shared__ float red[4];
    __shared__ float sh[HD];
    if ((d & 31) == 0) red[d >> 5] = ssq;
    __syncthreads();
    float tot = red[0] + red[1] + red[2] + red[3];

    float xn = v * rsqrtf(tot * (1.0f / HD) + 1e-6f) * w[d];
    sh[d] = xn;
    __syncthreads();

    float partner = (d < 64) ? -sh[d + 64] : sh[d - 64];
    float res = xn * cs[s * HD + d] + partner * sn[s * HD + d];

    __half h16 = __float2half(res);
    oh[oo + d] = h16;
    ol[oo + d] = __float2half(res - __half2float(h16));
}

// ---------------------------------------------------------------------------
// Tensor-core flash attention (wmma path, unchanged from R4 passing version)
// ---------------------------------------------------------------------------
#include <mma.h>
using namespace nvcuda;

#define QLD 136
#define SLD 132
#define PLD 72

#define OFF_QH 0
#define OFF_QL 17408
#define OFF_KH 34816
#define OFF_KL 52224
#define OFF_V  69632
#define OFF_S  87040
#define OFF_P  120832
#define OFF_O  130048
#define OFF_M  162816
#define OFF_L  163072
#define OFF_AL 163328
#define FLASH_SMEM 163584

__global__ void __launch_bounds__(256) flash_wmma(
    const __half* __restrict__ qh, const __half* __restrict__ ql,
    const __half* __restrict__ kh, const __half* __restrict__ kl,
    const __half* __restrict__ vv,
    __nv_bfloat16* __restrict__ oh, __nv_bfloat16* __restrict__ ol)
{
    extern __shared__ char smc[];
    __half* sQh = (__half*)(smc + OFF_QH);
    __half* sQl = (__half*)(smc + OFF_QL);
    __half* sKh = (__half*)(smc + OFF_KH);
    __half* sKl = (__half*)(smc + OFF_KL);
    __half* sV  = (__half*)(smc + OFF_V);
    float*  sS  = (float*)(smc + OFF_S);
    __half* sP  = (__half*)(smc + OFF_P);
    float*  sO  = (float*)(smc + OFF_O);
    float*  sM  = (float*)(smc + OFF_M);
    float*  sL  = (float*)(smc + OFF_L);
    float*  sA  = (float*)(smc + OFF_AL);

    const int h     = blockIdx.x;
    const int ptile = (int)gridDim.y - 1 - blockIdx.y;
    const int m0    = ptile << 6;
    const int kvh   = h >> 3;
    const int tid   = threadIdx.x;
    const int wid   = tid >> 5;
    const int rs    = wid >> 1;
    const int ch    = wid & 1;
    const float scale = 0.08838834764831845f;

    {
        uint32_t dqh = smem_u32(sQh), dql = smem_u32(sQl);
#pragma unroll
        for (int i = 0; i < 4; i++) {
            int idx = tid + (i << 8);
            int r = idx >> 4, c = idx & 15;
            size_t so = (size_t)(m0 + r) * NQ + h * HD + (c << 3);
            uint32_t off = r * (QLD * 2) + (c << 4);
            cpa16(dqh + off, qh + so);
            cpa16(dql + off, ql + so);
        }
        CPA_COMMIT();
    }
    for (int i = tid; i < 64 * 128 / 4; i += 256)
        ((float4*)sO)[i] = make_float4(0.f, 0.f, 0.f, 0.f);
    if (tid < 64) { sM[tid] = -1e30f; sL[tid] = 0.f; }
    CPA_WAIT0();
    __syncthreads();

    for (int kb = 0; kb <= ptile; kb++) {
        const int k0g = kb << 6;
        {
            uint32_t dkh = smem_u32(sKh), dkl = smem_u32(sKl), dv = smem_u32(sV);
#pragma unroll
            for (int i = 0; i < 4; i++) {
                int idx = tid + (i << 8);
                int r = idx >> 4, c = idx & 15;
                size_t so = (size_t)(k0g + r) * NKVD + kvh * HD + (c << 3);
                uint32_t off = r * (QLD * 2) + (c << 4);
                cpa16(dkh + off, kh + so);
                cpa16(dkl + off, kl + so);
                cpa16(dv + off,  vv + so);
            }
            CPA_COMMIT();
            CPA_WAIT0();
        }
        __syncthreads();

        {
            wmma::fragment<wmma::accumulator, 16, 16, 16, float> accS[2];
            wmma::fill_fragment(accS[0], 0.0f);
            wmma::fill_fragment(accS[1], 0.0f);
#pragma unroll
            for (int k0 = 0; k0 < 128; k0 += 16) {
                wmma::fragment<wmma::matrix_a, 16, 16, 16, __half, wmma::row_major> ah, al;
                wmma::load_matrix_sync(ah, sQh + rs * 16 * QLD + k0, QLD);
                wmma::load_matrix_sync(al, sQl + rs * 16 * QLD + k0, QLD);
#pragma unroll
                for (int j = 0; j < 2; j++) {
                    wmma::fragment<wmma::matrix_b, 16, 16, 16, __half, wmma::col_major> bh, bl;
                    int kcol = ch * 32 + j * 16;
                    wmma::load_matrix_sync(bh, sKh + kcol * QLD + k0, QLD);
                    wmma::load_matrix_sync(bl, sKl + kcol * QLD + k0, QLD);
                    wmma::mma_sync(accS[j], ah, bh, accS[j]);
                    wmma::mma_sync(accS[j], ah, bl, accS[j]);
                    wmma::mma_sync(accS[j], al, bh, accS[j]);
                }
            }
#pragma unroll
            for (int j = 0; j < 2; j++)
                wmma::store_matrix_sync(sS + rs * 16 * SLD + ch * 32 + j * 16,
                                        accS[j], SLD, wmma::mem_row_major);
        }
        __syncthreads();

        {
            const int r  = tid >> 2;
            const int q4 = tid & 3;
            float* srow = sS + r * SLD + q4 * 16;
            const int qglob = m0 + r;
            const int kbase = k0g + q4 * 16;

            float vals[16];
            float mx = -1e30f;
#pragma unroll
            for (int j = 0; j < 16; j++) {
                float s = srow[j];
                s = (kbase + j <= qglob) ? s * scale : -1e30f;
                vals[j] = s;
                mx = fmaxf(mx, s);
            }
            mx = fmaxf(mx, __shfl_xor_sync(0xffffffffu, mx, 1));
            mx = fmaxf(mx, __shfl_xor_sync(0xffffffffu, mx, 2));

            float mold = sM[r];
            float mnew = fmaxf(mold, mx);
            float alpha = fexp(mold - mnew);

            __half* prow = sP + r * PLD + q4 * 16;
            float lsum = 0.f;
#pragma unroll
            for (int j = 0; j < 16; j++) {
                float p = fexp(vals[j] - mnew);
                prow[j] = __float2half(p);
                lsum += p;
            }
            lsum += __shfl_xor_sync(0xffffffffu, lsum, 1);
            lsum += __shfl_xor_sync(0xffffffffu, lsum, 2);

            if (q4 == 0) {
                sM[r] = mnew;
                sL[r] = sL[r] * alpha + lsum;
                sA[r] = alpha;
            }
        }
        __syncthreads();

        {
            wmma::fragment<wmma::accumulator, 16, 16, 16, float> accO[4];
#pragma unroll
            for (int j = 0; j < 4; j++) wmma::fill_fragment(accO[j], 0.0f);
#pragma unroll
            for (int k0 = 0; k0 < 64; k0 += 16) {
                wmma::fragment<wmma::matrix_a, 16, 16, 16, __half, wmma::row_major> a;
                wmma::load_matrix_sync(a, sP + rs * 16 * PLD + k0, PLD);
#pragma unroll
                for (int j = 0; j < 4; j++) {
                    wmma::fragment<wmma::matrix_b, 16, 16, 16, __half, wmma::row_major> b;
                    wmma::load_matrix_sync(b, sV + k0 * QLD + ch * 64 + j * 16, QLD);
                    wmma::mma_sync(accO[j], a, b, accO[j]);
                }
            }
#pragma unroll
            for (int j = 0; j < 4; j++)
                wmma::store_matrix_sync(sS + rs * 16 * SLD + ch * 64 + j * 16,
                                        accO[j], SLD, wmma::mem_row_major);
        }
        __syncthreads();

        {
            const int r  = tid >> 2;
            const int c0 = (tid & 3) << 5;
            const float a = sA[r];
            float4* op = (float4*)(sO + r * 128 + c0);
            const float4* pv = (const float4*)(sS + r * SLD + c0);
#pragma unroll
            for (int j = 0; j < 8; j++) {
                float4 o = op[j], p = pv[j];
                o.x = o.x * a + p.x;
                o.y = o.y * a + p.y;
                o.z = o.z * a + p.z;
                o.w = o.w * a + p.w;
                op[j] = o;
            }
        }
        __syncthreads();
    }

    {
        const int r  = tid >> 2;
        const int c0 = (tid & 3) << 5;
        const float inv = 1.0f / sL[r];
        const size_t base = (size_t)(m0 + r) * NQ + h * HD + c0;
#pragma unroll
        for (int j = 0; j < 32; j++) {
            float o = sO[r * 128 + c0 + j] * inv;
            __nv_bfloat16 hi = __float2bfloat16(o);
            oh[base + j] = hi;
            ol[base + j] = __float2bfloat16(o - __bfloat162float(hi));
        }
    }
}

// ---------------------------------------------------------------------------
extern "C" void kernel_launch(void* const* d_in, const int* in_sizes, int n_in,
                              void* d_out, int out_size)
{
    (void)in_sizes; (void)n_in; (void)out_size;
    const float* x  = (const float*)d_in[0];
    const float* wq = (const float*)d_in[1];
    const float* wk = (const float*)d_in[2];
    const float* wv = (const float*)d_in[3];
    const float* wo = (const float*)d_in[4];
    const float* qn = (const float*)d_in[5];
    const float* kn = (const float*)d_in[6];
    const float* cs = (const float*)d_in[7];
    const float* sn = (const float*)d_in[8];
    float* out = (float*)d_out;

    float* qkv;
    cudaGetSymbolAddress((void**)&qkv, g_qkv);

    __nv_bfloat16 *xh, *xl, *wTh, *wTl, *woTh, *woTl, *ath, *atl;
    cudaGetSymbolAddress((void**)&xh,   g_xh);
    cudaGetSymbolAddress((void**)&xl,   g_xl);
    cudaGetSymbolAddress((void**)&wTh,  g_wqkvTh);
    cudaGetSymbolAddress((void**)&wTl,  g_wqkvTl);
    cudaGetSymbolAddress((void**)&woTh, g_woTh);
    cudaGetSymbolAddress((void**)&woTl, g_woTl);
    cudaGetSymbolAddress((void**)&ath,  g_ath);
    cudaGetSymbolAddress((void**)&atl,  g_atl);

    __half *q16h, *q16l, *k16h, *k16l, *v16;
    cudaGetSymbolAddress((void**)&q16h, g_q16h);
    cudaGetSymbolAddress((void**)&q16l, g_q16l);
    cudaGetSymbolAddress((void**)&k16h, g_k16h);
    cudaGetSymbolAddress((void**)&k16l, g_k16l);
    cudaGetSymbolAddress((void**)&v16,  g_v16);

    cudaFuncSetAttribute(gemm_mma_bf16x3,
                         cudaFuncAttributeMaxDynamicSharedMemorySize, GEMM_SMEM);
    cudaFuncSetAttribute(flash_wmma,
                         cudaFuncAttributeMaxDynamicSharedMemorySize, FLASH_SMEM);

    // Split activations; transpose+split weights into fused [5120][2048] buffer
    split_bf16<<<(S_LEN * HID + 255) / 256, 256>>>(x, xh, xl, S_LEN * HID);
    transpose_split<<<dim3(NQ / 32,   HID / 32), dim3(32, 8)>>>(
        wq, wTh, wTl, HID, NQ);
    transpose_split<<<dim3(NKVD / 32, HID / 32), dim3(32, 8)>>>(
        wk, wTh + (size_t)NQ * HID, wTl + (size_t)NQ * HID, HID, NKVD);
    transpose_split<<<dim3(NKVD / 32, HID / 32), dim3(32, 8)>>>(
        wv, wTh + (size_t)(NQ + NKVD) * HID, wTl + (size_t)(NQ + NKVD) * HID, HID, NKVD);
    transpose_split<<<dim3(HID / 32,  NQ / 32),  dim3(32, 8)>>>(wo, woTh, woTl, NQ, HID);

    // Fused QKV projection (raw HMMA bf16x3): [2048][5120]
    gemm_mma_bf16x3<<<dim3(NQKV / 128, S_LEN / 128), 256, GEMM_SMEM>>>(
        xh, xl, wTh, wTl, qkv, NQKV, HID);

    // RMSNorm + RoPE -> fp16 hi/lo; V -> fp16
    rmsnorm_rope_f16<<<S_LEN * NH,  128>>>(qkv, 0,         qn, cs, sn, NH,  q16h, q16l);
    rmsnorm_rope_f16<<<S_LEN * NKV, 128>>>(qkv, NQ,        kn, cs, sn, NKV, k16h, k16l);
    cvt_v16<<<(S_LEN * NKVD) / 256, 256>>>(qkv, v16);

    // Tensor-core causal GQA flash attention -> bf16 hi/lo
    flash_wmma<<<dim3(NH, S_LEN / 64), 256, FLASH_SMEM>>>(
        q16h, q16l, k16h, k16l, v16, ath, atl);

    // Output projection
    gemm_mma_bf16x3<<<dim3(HID / 128, S_LEN / 128), 256, GEMM_SMEM>>>(
        ath, atl, woTh, woTl, out, HID, NQ);
}

// round 6
// speedup vs baseline: 3.6284x; 1.0049x over previous
#include <cuda_runtime.h>
#include <cuda_bf16.h>
#include <cuda_fp16.h>
#include <cstdint>
#include <math.h>

#define S_LEN 2048
#define HID   2048
#define NH    32
#define NKV   4
#define HD    128
#define NQ    (NH * HD)    // 4096
#define NKVD  (NKV * HD)   // 512
#define NQKV  (NQ + 2 * NKVD)  // 5120

// ---------------------------------------------------------------------------
// Scratch (device globals — no allocation allowed)
// ---------------------------------------------------------------------------
__device__ float g_qkv[S_LEN * NQKV];

__device__ __nv_bfloat16 g_xh[S_LEN * HID];
__device__ __nv_bfloat16 g_xl[S_LEN * HID];
__device__ __nv_bfloat16 g_wqkvTh[NQKV * HID];
__device__ __nv_bfloat16 g_wqkvTl[NQKV * HID];
__device__ __nv_bfloat16 g_woTh[HID * NQ];
__device__ __nv_bfloat16 g_woTl[HID * NQ];
__device__ __nv_bfloat16 g_ath[S_LEN * NQ];
__device__ __nv_bfloat16 g_atl[S_LEN * NQ];

__device__ __half g_q16h[S_LEN * NQ];
__device__ __half g_q16l[S_LEN * NQ];
__device__ __half g_k16h[S_LEN * NKVD];
__device__ __half g_k16l[S_LEN * NKVD];
__device__ __half g_v16[S_LEN * NKVD];

// ---------------------------------------------------------------------------
// helpers
// ---------------------------------------------------------------------------
__device__ __forceinline__ uint32_t smem_u32(const void* p) {
    uint32_t a;
    asm("{ .reg .u64 t; cvta.to.shared.u64 t, %1; cvt.u32.u64 %0, t; }"
        : "=r"(a) : "l"(p));
    return a;
}

__device__ __forceinline__ void cpa16(uint32_t dst, const void* src) {
    asm volatile(
        "{\n\t.reg .u64 g;\n\tcvta.to.global.u64 g, %1;\n\t"
        "cp.async.cg.shared.global [%0], [g], 16;\n\t}"
        :: "r"(dst), "l"(src) : "memory");
}
#define CPA_COMMIT() asm volatile("cp.async.commit_group;" ::: "memory")
#define CPA_WAIT1()  asm volatile("cp.async.wait_group 1;" ::: "memory")
#define CPA_WAIT0()  asm volatile("cp.async.wait_group 0;" ::: "memory")

#define LDSM4(r, addr) \
    asm volatile("ldmatrix.sync.aligned.m8n8.x4.shared.b16 {%0,%1,%2,%3}, [%4];" \
        : "=r"((r)[0]), "=r"((r)[1]), "=r"((r)[2]), "=r"((r)[3]) : "r"(addr))

__device__ __forceinline__ void mma16816(float* d, const uint32_t* a,
                                         uint32_t b0, uint32_t b1) {
    asm volatile(
        "mma.sync.aligned.m16n8k16.row.col.f32.bf16.bf16.f32 "
        "{%0,%1,%2,%3}, {%4,%5,%6,%7}, {%8,%9}, {%0,%1,%2,%3};"
        : "+f"(d[0]), "+f"(d[1]), "+f"(d[2]), "+f"(d[3])
        : "r"(a[0]), "r"(a[1]), "r"(a[2]), "r"(a[3]), "r"(b0), "r"(b1));
}

// Fast exp on the FFMA pipe. Rel err < 3e-6 on [-87, 0].
__device__ __forceinline__ float fexp(float x) {
    x = fmaxf(x, -87.0f);
    float z  = fmaf(x, 1.44269504089f, 12582912.0f);
    float nf = z - 12582912.0f;
    float f  = fmaf(x, 1.44269504089f, -nf);
    float p  = 1.333355815e-3f;
    p = fmaf(p, f, 9.618129107e-3f);
    p = fmaf(p, f, 5.550410866e-2f);
    p = fmaf(p, f, 2.402265069e-1f);
    p = fmaf(p, f, 6.931471806e-1f);
    p = fmaf(p, f, 1.0f);
    int n = __float_as_int(z) - 0x4B400000;
    return __int_as_float(__float_as_int(p) + (n << 23));
}

// ---------------------------------------------------------------------------
// aux kernels
// ---------------------------------------------------------------------------
__global__ void split_bf16(const float* __restrict__ in,
                           __nv_bfloat16* __restrict__ oh,
                           __nv_bfloat16* __restrict__ ol, int n)
{
    int i = blockIdx.x * blockDim.x + threadIdx.x;
    if (i < n) {
        float x = in[i];
        __nv_bfloat16 h = __float2bfloat16(x);
        oh[i] = h;
        ol[i] = __float2bfloat16(x - __bfloat162float(h));
    }
}

__global__ void cvt_v16(const float* __restrict__ qkv, __half* __restrict__ out)
{
    int i = blockIdx.x * blockDim.x + threadIdx.x;
    int s = i >> 9, d = i & 511;
    out[i] = __float2half(qkv[(size_t)s * NQKV + NQ + NKVD + d]);
}

__global__ void transpose_split(const float* __restrict__ in,
                                __nv_bfloat16* __restrict__ oh,
                                __nv_bfloat16* __restrict__ ol, int R, int C)
{
    __shared__ float t[32][33];
    int c0 = blockIdx.x << 5, r0 = blockIdx.y << 5;
    int x = threadIdx.x, y = threadIdx.y;
#pragma unroll
    for (int j = y; j < 32; j += 8)
        t[j][x] = in[(size_t)(r0 + j) * C + c0 + x];
    __syncthreads();
#pragma unroll
    for (int j = y; j < 32; j += 8) {
        float v = t[x][j];
        __nv_bfloat16 h = __float2bfloat16(v);
        size_t o = (size_t)(c0 + j) * R + r0 + x;
        oh[o] = h;
        ol[o] = __float2bfloat16(v - __bfloat162float(h));
    }
}

// ---------------------------------------------------------------------------
// Raw-HMMA bf16x3 GEMM, 2 CTAs/SM version.
// CTA 128x128, 8 warps, warp tile 64x32. K chunks of 32, 2-stage cp.async.
// Smem rows 80 B (64 data + 16 pad) -> conflict-free ldmatrix (stride 20 words).
// Stage = 4 tiles x 10240 B = 40960 B; 2 stages = 81920 B -> 2 CTAs/SM.
// ---------------------------------------------------------------------------
#define RPAD_B 80
#define TILE_B (128 * RPAD_B)            // 10240
#define STG_B  (4 * TILE_B)              // 40960
#define GEMM_SMEM (2 * STG_B)            // 81920

__global__ void __launch_bounds__(256, 2) gemm_mma_bf16x3(
    const __nv_bfloat16* __restrict__ Ah, const __nv_bfloat16* __restrict__ Al,
    const __nv_bfloat16* __restrict__ Bh, const __nv_bfloat16* __restrict__ Bl,
    float* __restrict__ C, int N, int K)
{
    extern __shared__ char smraw[];
    const int tid  = threadIdx.x;
    const int wid  = tid >> 5, lane = tid & 31;
    const int m0 = blockIdx.y << 7, n0 = blockIdx.x << 7;
    const int wm = wid >> 2;             // 0..1  (64-row slab)
    const int wn = wid & 3;              // 0..3  (32-col slab)

    const uint32_t sbase = smem_u32(smraw);

    float acc[4][4][4];
#pragma unroll
    for (int i = 0; i < 4; i++)
#pragma unroll
        for (int j = 0; j < 4; j++)
#pragma unroll
            for (int r = 0; r < 4; r++) acc[i][j][r] = 0.0f;

    const uint32_t lrow = lane & 15;
    const uint32_t lkof = (lane >> 4) << 4;

    const __nv_bfloat16* gb[4] = {Ah, Al, Bh, Bl};
    const int gr0[4] = {m0, m0, n0, n0};
    const int nck = K >> 5;

    auto load_stage = [&](int ck, int s) {
        const int k0 = ck << 5;
        const uint32_t sb = sbase + s * STG_B;
#pragma unroll
        for (int t = 0; t < 4; t++) {
#pragma unroll
            for (int i = 0; i < 2; i++) {
                int idx = (i << 8) + tid;          // 0..511
                int row = idx >> 2, c = idx & 3;
                cpa16(sb + t * TILE_B + row * RPAD_B + c * 16,
                      gb[t] + (size_t)(gr0[t] + row) * K + k0 + c * 8);
            }
        }
        CPA_COMMIT();
    };

    load_stage(0, 0);

    for (int ck = 0; ck < nck; ck++) {
        if (ck + 1 < nck) { load_stage(ck + 1, (ck + 1) & 1); CPA_WAIT1(); }
        else             { CPA_WAIT0(); }
        __syncthreads();

        const uint32_t sb = sbase + (ck & 1) * STG_B;
        const uint32_t aHb = sb + (wm * 64 + lrow) * RPAD_B + lkof;
        const uint32_t aLb = aHb + TILE_B;
        const uint32_t bHb = sb + 2 * TILE_B + (wn * 32 + lrow) * RPAD_B + lkof;
        const uint32_t bLb = bHb + TILE_B;

#pragma unroll
        for (int kk = 0; kk < 2; kk++) {
            const uint32_t ko = kk * 32;
            uint32_t bh[2][4], bl[2][4];
#pragma unroll
            for (int np = 0; np < 2; np++) {
                LDSM4(bh[np], bHb + np * 16 * RPAD_B + ko);
                LDSM4(bl[np], bLb + np * 16 * RPAD_B + ko);
            }
#pragma unroll
            for (int mt = 0; mt < 4; mt++) {
                uint32_t ah[4], al[4];
                LDSM4(ah, aHb + mt * 16 * RPAD_B + ko);
                LDSM4(al, aLb + mt * 16 * RPAD_B + ko);
#pragma unroll
                for (int nt = 0; nt < 4; nt++) {
                    const int np = nt >> 1, sl = nt & 1;
                    mma16816(acc[mt][nt], ah, bh[np][sl], bh[np][sl + 2]);
                    mma16816(acc[mt][nt], ah, bl[np][sl], bl[np][sl + 2]);
                    mma16816(acc[mt][nt], al, bh[np][sl], bh[np][sl + 2]);
                }
            }
        }
        __syncthreads();
    }

    const int erow = (lane >> 2);
    const int ecol = (lane & 3) << 1;
#pragma unroll
    for (int mt = 0; mt < 4; mt++) {
#pragma unroll
        for (int nt = 0; nt < 4; nt++) {
            const int r = m0 + wm * 64 + mt * 16 + erow;
            const int c = n0 + wn * 32 + nt * 8 + ecol;
            *(float2*)(C + (size_t)r * N + c) =
                make_float2(acc[mt][nt][0], acc[mt][nt][1]);
            *(float2*)(C + (size_t)(r + 8) * N + c) =
                make_float2(acc[mt][nt][2], acc[mt][nt][3]);
        }
    }
}

// ---------------------------------------------------------------------------
// Fused RMSNorm + RoPE, reading a column slice of fused qkv -> fp16 hi/lo
// ---------------------------------------------------------------------------
__global__ __launch_bounds__(128) void rmsnorm_rope_f16(
    const float* __restrict__ qkv, int colOff, const float* __restrict__ w,
    const float* __restrict__ cs, const float* __restrict__ sn, int heads,
    __half* __restrict__ oh, __half* __restrict__ ol)
{
    const int b = blockIdx.x;
    const int s = b / heads;
    const int h = b - s * heads;
    const int d = threadIdx.x;

    const size_t io = (size_t)s * NQKV + colOff + h * HD;
    const size_t oo = ((size_t)s * heads + h) * HD;
    float v = qkv[io + d];

    float ssq = v * v;
#pragma unroll
    for (int off = 16; off > 0; off >>= 1)
        ssq += __shfl_xor_sync(0xffffffffu, ssq, off);

    __shared__ float red[4];
    __shared__ float sh[HD];
    if ((d & 31) == 0) red[d >> 5] = ssq;
    __syncthreads();
    float tot = red[0] + red[1] + red[2] + red[3];

    float xn = v * rsqrtf(tot * (1.0f / HD) + 1e-6f) * w[d];
    sh[d] = xn;
    __syncthreads();

    float partner = (d < 64) ? -sh[d + 64] : sh[d - 64];
    float res = xn * cs[s * HD + d] + partner * sn[s * HD + d];

    __half h16 = __float2half(res);
    oh[oo + d] = h16;
    ol[oo + d] = __float2half(res - __half2float(h16));
}

// ---------------------------------------------------------------------------
// Tensor-core flash attention with double-buffered K/V prefetch.
// ---------------------------------------------------------------------------
#include <mma.h>
using namespace nvcuda;

#define QLD 136
#define SLD 132
#define PLD 72

#define OFF_QH 0
#define OFF_QL 17408
#define OFF_KV 34816          // per-buf: KH +0, KL +17408, V +34816
#define KVBUF  52224          // stride between buf 0 and buf 1
#define OFF_S  139264
#define OFF_P  173056
#define OFF_O  182272
#define OFF_M  215040
#define OFF_L  215296
#define OFF_AL 215552
#define FLASH_SMEM 215808

__global__ void __launch_bounds__(256) flash_wmma(
    const __half* __restrict__ qh, const __half* __restrict__ ql,
    const __half* __restrict__ kh, const __half* __restrict__ kl,
    const __half* __restrict__ vv,
    __nv_bfloat16* __restrict__ oh, __nv_bfloat16* __restrict__ ol)
{
    extern __shared__ char smc[];
    __half* sQh = (__half*)(smc + OFF_QH);
    __half* sQl = (__half*)(smc + OFF_QL);
    float*  sS  = (float*)(smc + OFF_S);
    __half* sP  = (__half*)(smc + OFF_P);
    float*  sO  = (float*)(smc + OFF_O);
    float*  sM  = (float*)(smc + OFF_M);
    float*  sL  = (float*)(smc + OFF_L);
    float*  sA  = (float*)(smc + OFF_AL);

    const int h     = blockIdx.x;
    const int ptile = (int)gridDim.y - 1 - blockIdx.y;
    const int m0    = ptile << 6;
    const int kvh   = h >> 3;
    const int tid   = threadIdx.x;
    const int wid   = tid >> 5;
    const int rs    = wid >> 1;
    const int ch    = wid & 1;
    const float scale = 0.08838834764831845f;

    // KV tile loader -> buffer buf
    auto load_kv = [&](int kb, int buf) {
        const int k0g = kb << 6;
        const uint32_t base = smem_u32(smc) + OFF_KV + buf * KVBUF;
#pragma unroll
        for (int i = 0; i < 4; i++) {
            int idx = tid + (i << 8);
            int r = idx >> 4, c = idx & 15;
            size_t so = (size_t)(k0g + r) * NKVD + kvh * HD + (c << 3);
            uint32_t off = r * (QLD * 2) + (c << 4);
            cpa16(base + off,             kh + so);
            cpa16(base + 17408 + off,     kl + so);
            cpa16(base + 34816 + off,     vv + so);
        }
        CPA_COMMIT();
    };

    // Q load (group 0)
    {
        uint32_t dqh = smem_u32(sQh), dql = smem_u32(sQl);
#pragma unroll
        for (int i = 0; i < 4; i++) {
            int idx = tid + (i << 8);
            int r = idx >> 4, c = idx & 15;
            size_t so = (size_t)(m0 + r) * NQ + h * HD + (c << 3);
            uint32_t off = r * (QLD * 2) + (c << 4);
            cpa16(dqh + off, qh + so);
            cpa16(dql + off, ql + so);
        }
        CPA_COMMIT();
    }
    load_kv(0, 0);   // group 1

    for (int i = tid; i < 64 * 128 / 4; i += 256)
        ((float4*)sO)[i] = make_float4(0.f, 0.f, 0.f, 0.f);
    if (tid < 64) { sM[tid] = -1e30f; sL[tid] = 0.f; }

    for (int kb = 0; kb <= ptile; kb++) {
        const int k0g = kb << 6;
        const int buf = kb & 1;
        __half* sKh = (__half*)(smc + OFF_KV + buf * KVBUF);
        __half* sKl = (__half*)(smc + OFF_KV + buf * KVBUF + 17408);
        __half* sV  = (__half*)(smc + OFF_KV + buf * KVBUF + 34816);

        if (kb < ptile) { load_kv(kb + 1, buf ^ 1); CPA_WAIT1(); }
        else            { CPA_WAIT0(); }
        __syncthreads();

        // --- QK^T ---
        {
            wmma::fragment<wmma::accumulator, 16, 16, 16, float> accS[2];
            wmma::fill_fragment(accS[0], 0.0f);
            wmma::fill_fragment(accS[1], 0.0f);
#pragma unroll
            for (int k0 = 0; k0 < 128; k0 += 16) {
                wmma::fragment<wmma::matrix_a, 16, 16, 16, __half, wmma::row_major> ah, al;
                wmma::load_matrix_sync(ah, sQh + rs * 16 * QLD + k0, QLD);
                wmma::load_matrix_sync(al, sQl + rs * 16 * QLD + k0, QLD);
#pragma unroll
                for (int j = 0; j < 2; j++) {
                    wmma::fragment<wmma::matrix_b, 16, 16, 16, __half, wmma::col_major> bh, bl;
                    int kcol = ch * 32 + j * 16;
                    wmma::load_matrix_sync(bh, sKh + kcol * QLD + k0, QLD);
                    wmma::load_matrix_sync(bl, sKl + kcol * QLD + k0, QLD);
                    wmma::mma_sync(accS[j], ah, bh, accS[j]);
                    wmma::mma_sync(accS[j], ah, bl, accS[j]);
                    wmma::mma_sync(accS[j], al, bh, accS[j]);
                }
            }
#pragma unroll
            for (int j = 0; j < 2; j++)
                wmma::store_matrix_sync(sS + rs * 16 * SLD + ch * 32 + j * 16,
                                        accS[j], SLD, wmma::mem_row_major);
        }
        __syncthreads();

        // --- online softmax ---
        {
            const int r  = tid >> 2;
            const int q4 = tid & 3;
            float* srow = sS + r * SLD + q4 * 16;
            const int qglob = m0 + r;
            const int kbase = k0g + q4 * 16;

            float vals[16];
            float mx = -1e30f;
#pragma unroll
            for (int j = 0; j < 16; j++) {
                float s = srow[j];
                s = (kbase + j <= qglob) ? s * scale : -1e30f;
                vals[j] = s;
                mx = fmaxf(mx, s);
            }
            mx = fmaxf(mx, __shfl_xor_sync(0xffffffffu, mx, 1));
            mx = fmaxf(mx, __shfl_xor_sync(0xffffffffu, mx, 2));

            float mold = sM[r];
            float mnew = fmaxf(mold, mx);
            float alpha = fexp(mold - mnew);

            __half* prow = sP + r * PLD + q4 * 16;
            float lsum = 0.f;
#pragma unroll
            for (int j = 0; j < 16; j++) {
                float p = fexp(vals[j] - mnew);
                prow[j] = __float2half(p);
                lsum += p;
            }
            lsum += __shfl_xor_sync(0xffffffffu, lsum, 1);
            lsum += __shfl_xor_sync(0xffffffffu, lsum, 2);

            if (q4 == 0) {
                sM[r] = mnew;
                sL[r] = sL[r] * alpha + lsum;
                sA[r] = alpha;
            }
        }
        __syncthreads();

        // --- P @ V ---
        {
            wmma::fragment<wmma::accumulator, 16, 16, 16, float> accO[4];
#pragma unroll
            for (int j = 0; j < 4; j++) wmma::fill_fragment(accO[j], 0.0f);
#pragma unroll
            for (int k0 = 0; k0 < 64; k0 += 16) {
                wmma::fragment<wmma::matrix_a, 16, 16, 16, __half, wmma::row_major> a;
                wmma::load_matrix_sync(a, sP + rs * 16 * PLD + k0, PLD);
#pragma unroll
                for (int j = 0; j < 4; j++) {
                    wmma::fragment<wmma::matrix_b, 16, 16, 16, __half, wmma::row_major> b;
                    wmma::load_matrix_sync(b, sV + k0 * QLD + ch * 64 + j * 16, QLD);
                    wmma::mma_sync(accO[j], a, b, accO[j]);
                }
            }
#pragma unroll
            for (int j = 0; j < 4; j++)
                wmma::store_matrix_sync(sS + rs * 16 * SLD + ch * 64 + j * 16,
                                        accO[j], SLD, wmma::mem_row_major);
        }
        __syncthreads();

        // --- O = O*alpha + PV ---
        {
            const int r  = tid >> 2;
            const int c0 = (tid & 3) << 5;
            const float a = sA[r];
            float4* op = (float4*)(sO + r * 128 + c0);
            const float4* pv = (const float4*)(sS + r * SLD + c0);
#pragma unroll
            for (int j = 0; j < 8; j++) {
                float4 o = op[j], p = pv[j];
                o.x = o.x * a + p.x;
                o.y = o.y * a + p.y;
                o.z = o.z * a + p.z;
                o.w = o.w * a + p.w;
                op[j] = o;
            }
        }
        __syncthreads();
    }

    {
        const int r  = tid >> 2;
        const int c0 = (tid & 3) << 5;
        const float inv = 1.0f / sL[r];
        const size_t base = (size_t)(m0 + r) * NQ + h * HD + c0;
#pragma unroll
        for (int j = 0; j < 32; j++) {
            float o = sO[r * 128 + c0 + j] * inv;
            __nv_bfloat16 hi = __float2bfloat16(o);
            oh[base + j] = hi;
            ol[base + j] = __float2bfloat16(o - __bfloat162float(hi));
        }
    }
}

// ---------------------------------------------------------------------------
extern "C" void kernel_launch(void* const* d_in, const int* in_sizes, int n_in,
                              void* d_out, int out_size)
{
    (void)in_sizes; (void)n_in; (void)out_size;
    const float* x  = (const float*)d_in[0];
    const float* wq = (const float*)d_in[1];
    const float* wk = (const float*)d_in[2];
    const float* wv = (const float*)d_in[3];
    const float* wo = (const float*)d_in[4];
    const float* qn = (const float*)d_in[5];
    const float* kn = (const float*)d_in[6];
    const float* cs = (const float*)d_in[7];
    const float* sn = (const float*)d_in[8];
    float* out = (float*)d_out;

    float* qkv;
    cudaGetSymbolAddress((void**)&qkv, g_qkv);

    __nv_bfloat16 *xh, *xl, *wTh, *wTl, *woTh, *woTl, *ath, *atl;
    cudaGetSymbolAddress((void**)&xh,   g_xh);
    cudaGetSymbolAddress((void**)&xl,   g_xl);
    cudaGetSymbolAddress((void**)&wTh,  g_wqkvTh);
    cudaGetSymbolAddress((void**)&wTl,  g_wqkvTl);
    cudaGetSymbolAddress((void**)&woTh, g_woTh);
    cudaGetSymbolAddress((void**)&woTl, g_woTl);
    cudaGetSymbolAddress((void**)&ath,  g_ath);
    cudaGetSymbolAddress((void**)&atl,  g_atl);

    __half *q16h, *q16l, *k16h, *k16l, *v16;
    cudaGetSymbolAddress((void**)&q16h, g_q16h);
    cudaGetSymbolAddress((void**)&q16l, g_q16l);
    cudaGetSymbolAddress((void**)&k16h, g_k16h);
    cudaGetSymbolAddress((void**)&k16l, g_k16l);
    cudaGetSymbolAddress((void**)&v16,  g_v16);

    cudaFuncSetAttribute(gemm_mma_bf16x3,
                         cudaFuncAttributeMaxDynamicSharedMemorySize, GEMM_SMEM);
    cudaFuncSetAttribute(flash_wmma,
                         cudaFuncAttributeMaxDynamicSharedMemorySize, FLASH_SMEM);

    split_bf16<<<(S_LEN * HID + 255) / 256, 256>>>(x, xh, xl, S_LEN * HID);
    transpose_split<<<dim3(NQ / 32,   HID / 32), dim3(32, 8)>>>(
        wq, wTh, wTl, HID, NQ);
    transpose_split<<<dim3(NKVD / 32, HID / 32), dim3(32, 8)>>>(
        wk, wTh + (size_t)NQ * HID, wTl + (size_t)NQ * HID, HID, NKVD);
    transpose_split<<<dim3(NKVD / 32, HID / 32), dim3(32, 8)>>>(
        wv, wTh + (size_t)(NQ + NKVD) * HID, wTl + (size_t)(NQ + NKVD) * HID, HID, NKVD);
    transpose_split<<<dim3(HID / 32,  NQ / 32),  dim3(32, 8)>>>(wo, woTh, woTl, NQ, HID);

    // Fused QKV projection
    gemm_mma_bf16x3<<<dim3(NQKV / 128, S_LEN / 128), 256, GEMM_SMEM>>>(
        xh, xl, wTh, wTl, qkv, NQKV, HID);

    // RMSNorm + RoPE -> fp16 hi/lo; V -> fp16
    rmsnorm_rope_f16<<<S_LEN * NH,  128>>>(qkv, 0,  qn, cs, sn, NH,  q16h, q16l);
    rmsnorm_rope_f16<<<S_LEN * NKV, 128>>>(qkv, NQ, kn, cs, sn, NKV, k16h, k16l);
    cvt_v16<<<(S_LEN * NKVD) / 256, 256>>>(qkv, v16);

    // Flash attention
    flash_wmma<<<dim3(NH, S_LEN / 64), 256, FLASH_SMEM>>>(
        q16h, q16l, k16h, k16l, v16, ath, atl);

    // Output projection
    gemm_mma_bf16x3<<<dim3(HID / 128, S_LEN / 128), 256, GEMM_SMEM>>>(
        ath, atl, woTh, woTl, out, HID, NQ);
}